// round 3
// baseline (speedup 1.0000x reference)
#include <cuda_runtime.h>
#include <math_constants.h>

#define V 100000
#define H 256
#define T_STEPS 64
#define RPB 256
#define G ((V + RPB - 1) / RPB)   /* 391 */
#define KTOP 10
#define NC (G * KTOP)

#define OUT_SEL   ((size_t)T_STEPS * V)
#define OUT_VAL   (OUT_SEL + T_STEPS)
#define OUT_HIT   (OUT_VAL + T_STEPS)
#define OUT_HIST  (OUT_HIT + T_STEPS)

// ---------------- device scratch (no allocations allowed) ----------------
__device__ __align__(16) float g_hist[V];
__device__ __align__(16) float g_logits[2][V];
__device__ __align__(16) float g_cell[H];
__device__ __align__(16) float g_proc[H];
__device__ __align__(16) float g_gbias[H];
__device__ float g_blkmax[G];
__device__ float g_blksum[G];
__device__ float g_candv[NC];
__device__ int   g_candi[NC];
__device__ float g_gmax[2];
__device__ float g_invZ[2];

__device__ __forceinline__ float sigmoidf_(float x){ return 1.f/(1.f+expf(-x)); }

// ---------------- init: hist = user_masking ----------------
__global__ __launch_bounds__(RPB) void k_init(const float* __restrict__ masking){
  int v = blockIdx.x*blockDim.x + threadIdx.x;
  if (v < V) g_hist[v] = masking[v];
}

// ---------------- proc_mem = tanh(mem @ mem_W.T) : one block per h ----------------
__global__ __launch_bounds__(256) void k_procmem(const float* __restrict__ mem, const float* __restrict__ memW){
  int h = blockIdx.x;
  int tid = threadIdx.x;
  const float4* m4 = (const float4*)mem;
  const float4* w4 = (const float4*)(memW + (size_t)h * V);
  float s = 0.f;
  for (int i = tid; i < V/4; i += blockDim.x){
    float4 a = m4[i], b = w4[i];
    s += a.x*b.x + a.y*b.y + a.z*b.z + a.w*b.w;
  }
  __shared__ float red[256];
  red[tid]=s; __syncthreads();
  for (int st=128; st; st>>=1){ if (tid<st) red[tid]+=red[tid+st]; __syncthreads(); }
  if (tid==0) g_proc[h] = tanhf(red[0]);
}

// ---------------- gbias = -(proc @ fg_mem_W.T + fg_mem_b) ----------------
__global__ __launch_bounds__(256) void k_prep(const float* __restrict__ fgmW, const float* __restrict__ fgmb){
  int i = threadIdx.x;
  const float4* wr = (const float4*)(fgmW + i*H);
  const float4* pr = (const float4*)g_proc;
  float s = 0.f;
  #pragma unroll
  for (int k=0;k<H/4;k++){ float4 w=wr[k], p=pr[k]; s += w.x*p.x+w.y*p.y+w.z*p.z+w.w*p.w; }
  g_gbias[i] = -(s + fgmb[i]);
}

// ---------------- GRU(x2) + gate + cell + value : expects 1024 threads ----------------
__device__ __forceinline__ void gru_and_cell(
    const float* __restrict__ Wih, const float* __restrict__ bih, const float* __restrict__ bhh,
    const float* __restrict__ fgcW, const float* __restrict__ valW, const float* __restrict__ valb,
    float* __restrict__ out, int tstep,
    float* sx, float* sgx, float* spart)
{
  int tid = threadIdx.x;
  __syncthreads();   // sx ready
  #pragma unroll
  for (int l=0;l<2;l++){
    const float* W = Wih + (size_t)l*3*H*H;
    #pragma unroll
    for (int k=0;k<3;k++){
      int u = tid + k*1024;          // 3072 units: (row, quarter)
      int row = u >> 2, ch = u & 3;
      const float4* wr = (const float4*)(W + row*H + ch*64);
      const float4* xr = (const float4*)sx + ch*16;
      float s = 0.f;
      #pragma unroll
      for (int i=0;i<16;i++){
        float4 w=wr[i], x=xr[i];
        s += w.x*x.x + w.y*x.y + w.z*x.z + w.w*x.w;
      }
      spart[u]=s;
    }
    __syncthreads();
    if (tid < 3*H) sgx[tid] = spart[4*tid]+spart[4*tid+1]+spart[4*tid+2]+spart[4*tid+3];
    __syncthreads();
    float nx = 0.f;
    if (tid < H){
      const float* bi = bih + l*3*H;
      const float* bh = bhh + l*3*H;
      float r  = sigmoidf_(sgx[tid]       + bi[tid]       + bh[tid]);
      float zz = sigmoidf_(sgx[H+tid]     + bi[H+tid]     + bh[H+tid]);
      float n  = tanhf   (sgx[2*H+tid]    + bi[2*H+tid]   + r*bh[2*H+tid]);
      nx = (1.f - zz) * n;
    }
    __syncthreads();
    if (tid < H) sx[tid] = nx;
    __syncthreads();
  }
  // gate: 1024 units = 256 rows x 4 quarters
  {
    int row = tid >> 2, ch = tid & 3;
    const float4* wr = (const float4*)(fgcW + row*H + ch*64);
    const float4* xr = (const float4*)sx + ch*16;
    float s = 0.f;
    #pragma unroll
    for (int i=0;i<16;i++){ float4 w=wr[i], x=xr[i]; s += w.x*x.x+w.y*x.y+w.z*x.z+w.w*x.w; }
    spart[tid]=s;
  }
  __syncthreads();
  if (tid < H){
    float d = spart[4*tid]+spart[4*tid+1]+spart[4*tid+2]+spart[4*tid+3];
    float gate = sigmoidf_(g_gbias[tid] + d);
    float cell = gate*g_proc[tid] + (1.f-gate)*sx[tid];
    g_cell[tid] = cell;
    sgx[tid] = cell;
  }
  __syncthreads();
  if (tid < H) spart[tid] = valW[tid]*sgx[tid];
  __syncthreads();
  for (int st=128; st; st>>=1){ if (tid<st) spart[tid]+=spart[tid+st]; __syncthreads(); }
  if (tid==0) out[OUT_VAL + tstep] = spart[0] + valb[0];
}

// ---------------- step 0 state ----------------
__global__ __launch_bounds__(1024, 1) void k_cell0(const float* __restrict__ emb,
                        const float* __restrict__ Wih, const float* __restrict__ bih,
                        const float* __restrict__ bhh, const float* __restrict__ fgcW,
                        const float* __restrict__ valW, const float* __restrict__ valb,
                        float* __restrict__ out){
  __shared__ __align__(16) float sx[H];
  __shared__ float sgx[3*H];
  __shared__ __align__(16) float spart[3*1024];
  int tid = threadIdx.x;
  if (tid < H) sx[tid] = emb[tid];   // emb_table[0] * s_hit(=1.0)
  gru_and_cell(Wih,bih,bhh,fgcW,valW,valb,out,0,sx,sgx,spart);
}

// ---------------- big step kernel: norm prev probs + logits + block stats + block top-10 ----------------
__global__ __launch_bounds__(RPB) void k_big(const float* __restrict__ fcW, const float* __restrict__ fcb,
                      float* __restrict__ out, int t){
  __shared__ __align__(16) float scell[H];
  __shared__ float slog[RPB];
  __shared__ float sval[RPB];
  __shared__ int   sidx[RPB];
  __shared__ float rv[RPB];
  __shared__ int   ri[RPB];
  int tid = threadIdx.x;
  int par = t & 1;
  int base = blockIdx.x * RPB;

  if (tid < H) scell[tid] = g_cell[tid];

  // fused normalization of previous step's probs (ping-pong logits buffer)
  if (t > 0){
    int v = base + tid;
    if (v < V){
      float gm = g_gmax[par^1];
      float iz = g_invZ[par^1];
      out[(size_t)(t-1)*V + v] = expf(g_logits[par^1][v]-gm)*iz;
    }
  }
  __syncthreads();

  // logits: one warp per row, fully-coalesced float4 loads
  int warp = tid >> 5, lane = tid & 31;
  const float4* sc4 = (const float4*)scell;
  float4 c0 = sc4[lane], c1 = sc4[lane+32];
  for (int r = warp; r < RPB; r += 8){
    int v = base + r;
    float s = 0.f;
    if (v < V){
      const float4* wr = (const float4*)(fcW + (size_t)v*H);
      float4 a = wr[lane], b = wr[lane+32];
      s = a.x*c0.x + a.y*c0.y + a.z*c0.z + a.w*c0.w
        + b.x*c1.x + b.y*c1.y + b.z*c1.z + b.w*c1.w;
    }
    #pragma unroll
    for (int off=16; off; off>>=1) s += __shfl_down_sync(0xffffffffu, s, off);
    if (lane == 0){
      float lg = -CUDART_INF_F;
      if (v < V){ lg = s + fcb[v]; g_logits[par][v] = lg; }
      slog[r] = lg;
    }
  }
  __syncthreads();

  // block max
  rv[tid] = slog[tid]; __syncthreads();
  for (int st=128; st; st>>=1){ if (tid<st) rv[tid]=fmaxf(rv[tid],rv[tid+st]); __syncthreads(); }
  float bmax = rv[0]; __syncthreads();
  // block sum of exp
  rv[tid] = (base+tid < V) ? expf(slog[tid]-bmax) : 0.f; __syncthreads();
  for (int st=128; st; st>>=1){ if (tid<st) rv[tid]+=rv[tid+st]; __syncthreads(); }
  if (tid==0){ g_blkmax[blockIdx.x]=bmax; g_blksum[blockIdx.x]=rv[0]; }

  // masked top-10 of this block's rows (ranking by logit == ranking by probs*hist)
  {
    int v = base + tid;
    bool ok = (v < V) && (g_hist[v] != 0.f);
    sval[tid] = ok ? slog[tid] : -CUDART_INF_F;
    sidx[tid] = v;
  }
  __syncthreads();
  for (int it=0; it<KTOP; it++){
    rv[tid]=sval[tid]; ri[tid]=sidx[tid]; __syncthreads();
    for (int st=128; st; st>>=1){
      if (tid<st){
        float ov=rv[tid+st]; int oi=ri[tid+st];
        if (ov>rv[tid] || (ov==rv[tid] && oi<ri[tid])){ rv[tid]=ov; ri[tid]=oi; }
      }
      __syncthreads();
    }
    if (tid==0){
      g_candv[blockIdx.x*KTOP+it]=rv[0];
      g_candi[blockIdx.x*KTOP+it]=ri[0];
      sval[ri[0]-base] = -CUDART_INF_F;
    }
    __syncthreads();
  }
}

// ---------------- small step kernel: softmax reduce + top-10 merge + select + next state ----------------
__global__ __launch_bounds__(1024, 1) void k_small(const float* __restrict__ interesting, const float* __restrict__ emb,
                        const float* __restrict__ Wih, const float* __restrict__ bih,
                        const float* __restrict__ bhh, const float* __restrict__ fgcW,
                        const float* __restrict__ valW, const float* __restrict__ valb,
                        float* __restrict__ out, int t){
  __shared__ __align__(16) float sx[H];
  __shared__ float sgx[3*H];
  __shared__ __align__(16) float spart[3*1024];
  __shared__ float s_wv[32]; __shared__ int s_wi[32]; __shared__ int s_wo[32];
  __shared__ int s_topi[KTOP];
  __shared__ int s_winner;
  __shared__ int s_sel; __shared__ float s_sign;
  int tid = threadIdx.x;
  int par = t & 1;
  int lane = tid & 31, warp = tid >> 5;

  // Phase 1: global softmax max & Z
  float m = -CUDART_INF_F;
  for (int i=tid;i<G;i+=1024) m = fmaxf(m, g_blkmax[i]);
  spart[tid]=m; __syncthreads();
  for (int st=512; st; st>>=1){ if(tid<st) spart[tid]=fmaxf(spart[tid],spart[tid+st]); __syncthreads(); }
  float gmax = spart[0]; __syncthreads();
  float z = 0.f;
  for (int i=tid;i<G;i+=1024) z += g_blksum[i]*expf(g_blkmax[i]-gmax);
  spart[tid]=z; __syncthreads();
  for (int st=512; st; st>>=1){ if(tid<st) spart[tid]+=spart[tid+st]; __syncthreads(); }
  if (tid==0){ g_gmax[par]=gmax; g_invZ[par]=1.f/spart[0]; }

  // Phase 2: global top-10 merge (per-thread sorted lists + tournament)
  float lv[KTOP]; int li[KTOP];
  #pragma unroll
  for (int k=0;k<KTOP;k++){ lv[k]=-CUDART_INF_F; li[k]=0x7FFFFFFF; }
  for (int i=tid;i<NC;i+=1024){
    float v=g_candv[i]; int ix=g_candi[i];
    if (v>lv[KTOP-1] || (v==lv[KTOP-1] && ix<li[KTOP-1])){
      int p=KTOP-1;
      while (p>0 && (lv[p-1]<v || (lv[p-1]==v && li[p-1]>ix))){
        lv[p]=lv[p-1]; li[p]=li[p-1]; p--;
      }
      lv[p]=v; li[p]=ix;
    }
  }
  int ptr = 0;
  __syncthreads();
  for (int r=0;r<KTOP;r++){
    float v = (ptr<KTOP)? lv[ptr] : -CUDART_INF_F;
    int ix = (ptr<KTOP)? li[ptr] : 0x7FFFFFFF;
    int src = tid;
    #pragma unroll
    for (int off=16; off; off>>=1){
      float ov = __shfl_down_sync(0xffffffffu, v, off);
      int oi = __shfl_down_sync(0xffffffffu, ix, off);
      int os = __shfl_down_sync(0xffffffffu, src, off);
      if (ov>v || (ov==v && oi<ix)){ v=ov; ix=oi; src=os; }
    }
    if (lane==0){ s_wv[warp]=v; s_wi[warp]=ix; s_wo[warp]=src; }
    __syncthreads();
    if (warp==0){
      float v2=s_wv[lane]; int ix2=s_wi[lane]; int src2=s_wo[lane];
      #pragma unroll
      for (int off=16; off; off>>=1){
        float ov = __shfl_down_sync(0xffffffffu, v2, off);
        int oi = __shfl_down_sync(0xffffffffu, ix2, off);
        int os = __shfl_down_sync(0xffffffffu, src2, off);
        if (ov>v2 || (ov==v2 && oi<ix2)){ v2=ov; ix2=oi; src2=os; }
      }
      if (lane==0){ s_topi[r]=ix2; s_winner=src2; }
    }
    __syncthreads();
    if (tid == s_winner) ptr++;
    __syncthreads();
  }

  // Phase 3: selection logic (matches reference score/argmax semantics)
  if (tid==0){
    int first = -1;
    #pragma unroll
    for (int r=0;r<KTOP;r++){
      if (first<0 && interesting[s_topi[r]] > 0.f) first = r;
    }
    int hit = (first>=0);
    int sel = hit ? s_topi[first] : s_topi[0];
    out[OUT_SEL+t] = (float)sel;
    out[OUT_HIT+t] = hit ? 1.f : 0.f;
    if (hit) g_hist[sel] -= 1.f;
    s_sel = sel;
    s_sign = hit ? 1.f : -1.f;   // out_emb = (2*hit-1)*emb
  }
  __syncthreads();

  // Phase 4: next input embedding -> GRU -> cell_{t+1}, value_{t+1}
  if (t+1 < T_STEPS){
    if (tid < H) sx[tid] = s_sign * emb[(size_t)s_sel*H + tid];
    gru_and_cell(Wih,bih,bhh,fgcW,valW,valb,out,t+1,sx,sgx,spart);
  }
}

// ---------------- final: normalize last step's probs + dump hist ----------------
__global__ __launch_bounds__(RPB) void k_final(float* __restrict__ out){
  int v = blockIdx.x*blockDim.x + threadIdx.x;
  if (v < V){
    int par = (T_STEPS-1) & 1;
    float gm = g_gmax[par];
    float iz = g_invZ[par];
    out[(size_t)(T_STEPS-1)*V + v] = expf(g_logits[par][v]-gm)*iz;
    out[OUT_HIST + v] = g_hist[v];
  }
}

extern "C" void kernel_launch(void* const* d_in, const int* in_sizes, int n_in,
                              void* d_out, int out_size){
  (void)in_sizes; (void)n_in; (void)out_size;
  const float* interesting = (const float*)d_in[0];
  const float* masking     = (const float*)d_in[1];
  const float* mem         = (const float*)d_in[2];
  const float* emb         = (const float*)d_in[3];
  const float* Wih         = (const float*)d_in[4];
  /* d_in[5] = gru_Whh unused (hidden state is always zero) */
  const float* bih         = (const float*)d_in[6];
  const float* bhh         = (const float*)d_in[7];
  const float* fcW         = (const float*)d_in[8];
  const float* fcb         = (const float*)d_in[9];
  const float* valW        = (const float*)d_in[10];
  const float* valb        = (const float*)d_in[11];
  const float* memW        = (const float*)d_in[12];
  const float* fgmW        = (const float*)d_in[13];
  const float* fgmb        = (const float*)d_in[14];
  const float* fgcW        = (const float*)d_in[15];
  /* d_in[16] = sequence_length (fixed 64 in this dataset) */
  float* out = (float*)d_out;

  k_init<<<G, RPB>>>(masking);
  k_procmem<<<H, 256>>>(mem, memW);
  k_prep<<<1, 256>>>(fgmW, fgmb);
  k_cell0<<<1, 1024>>>(emb, Wih, bih, bhh, fgcW, valW, valb, out);
  for (int t=0; t<T_STEPS; t++){
    k_big<<<G, RPB>>>(fcW, fcb, out, t);
    k_small<<<1, 1024>>>(interesting, emb, Wih, bih, bhh, fgcW, valW, valb, out, t);
  }
  k_final<<<G, RPB>>>(out);
}

// round 4
// speedup vs baseline: 1.6421x; 1.6421x over previous
#include <cuda_runtime.h>
#include <math_constants.h>

#define V 100000
#define H 256
#define T_STEPS 64
#define NB 120
#define TPB 512
#define RPC 834              /* ceil(V/NB) */
#define KTOP 10
#define NC (NB*KTOP)         /* 1200 */
#define HPC 3
#define NGRU 86              /* ceil(H/HPC) */

#define OUT_SEL   ((size_t)T_STEPS * V)
#define OUT_VAL   (OUT_SEL + T_STEPS)
#define OUT_HIT   (OUT_VAL + T_STEPS)
#define OUT_HIST  (OUT_HIT + T_STEPS)

// ---------------- device scratch ----------------
__device__ __align__(16) float g_hist[V];
__device__ __align__(16) float g_logits[2][V];
__device__ __align__(16) float g_cell[H];
__device__ __align__(16) float g_proc[H];
__device__ __align__(16) float g_gbias[H];
__device__ __align__(16) float g_xa[H];
__device__ __align__(16) float g_xb[H];
__device__ __align__(16) float g_xc[H];
__device__ float g_blkmax[NB];
__device__ float g_blksum[NB];
__device__ float g_candv[NC];
__device__ int   g_candi[NC];
__device__ float g_gmax[2];
__device__ float g_invZ[2];
__device__ unsigned g_count;     // zero-init; self-wrapping
__device__ unsigned g_release;   // monotonic across launches

__device__ __forceinline__ float sigmoidf_(float x){ return 1.f/(1.f+expf(-x)); }

// software grid barrier: monotonic release counter, per-CTA epoch/base in smem
__device__ __forceinline__ void gsync(unsigned* s_eb){ // s_eb[0]=epoch, s_eb[1]=base
  __syncthreads();
  if (threadIdx.x == 0){
    unsigned e = ++s_eb[0];
    __threadfence();
    unsigned prev = atomicInc(&g_count, NB-1u);
    if (prev == NB-1u){
      __threadfence();
      *(volatile unsigned*)&g_release = s_eb[1] + e;
    } else {
      while (*(volatile unsigned*)&g_release - s_eb[1] < e) { }
      __threadfence();
    }
  }
  __syncthreads();
}

// one GRU layer for this CTA's owned h's (weights in smem, x via global)
__device__ __forceinline__ void gru_layer(const float* Wsm, const float* xin_g,
                                          float* xout_g, const float* bi,
                                          const float* bh, int c,
                                          float* sx, float* sgx){
  int tid = threadIdx.x, lane = tid & 31, warp = tid >> 5;
  if (tid < H) sx[tid] = __ldcg(&xin_g[tid]);
  __syncthreads();
  if (warp < 3*HPC){
    int a = warp / 3;
    int h = c*HPC + a;
    float s = 0.f;
    if (h < H){
      const float4* wr = (const float4*)(Wsm + warp*H);
      const float4* xr = (const float4*)sx;
      float4 wv = wr[lane],    xv = xr[lane];
      s  = wv.x*xv.x + wv.y*xv.y + wv.z*xv.z + wv.w*xv.w;
      wv = wr[lane+32]; xv = xr[lane+32];
      s += wv.x*xv.x + wv.y*xv.y + wv.z*xv.z + wv.w*xv.w;
    }
    #pragma unroll
    for (int off=16; off; off>>=1) s += __shfl_down_sync(0xffffffffu, s, off);
    if (lane == 0) sgx[warp] = s;
  }
  __syncthreads();
  if (tid < HPC){
    int h = c*HPC + tid;
    if (h < H){
      float r  = sigmoidf_(sgx[tid*3+0] + bi[h]     + bh[h]);
      float z  = sigmoidf_(sgx[tid*3+1] + bi[H+h]   + bh[H+h]);
      float n  = tanhf   (sgx[tid*3+2] + bi[2*H+h] + r*bh[2*H+h]);
      xout_g[h] = (1.f - z) * n;
    }
  }
}

__global__ __launch_bounds__(TPB, 1)
void k_persist(const float* __restrict__ interesting, const float* __restrict__ masking,
               const float* __restrict__ mem, const float* __restrict__ emb,
               const float* __restrict__ Wih, const float* __restrict__ bih,
               const float* __restrict__ bhh, const float* __restrict__ fcW,
               const float* __restrict__ fcb, const float* __restrict__ valW,
               const float* __restrict__ valb, const float* __restrict__ memW,
               const float* __restrict__ fgmW, const float* __restrict__ fgmb,
               const float* __restrict__ fgcW, float* __restrict__ out){
  __shared__ __align__(16) float scell[H];      // also GRU sx
  __shared__ float sb[RPC];                     // fcb slice (persists)
  __shared__ float slog[RPC];
  __shared__ __align__(16) float w0[3*HPC*H];   // layer0 rows
  __shared__ __align__(16) float w1[3*HPC*H];   // layer1 rows
  __shared__ __align__(16) float wg[HPC*H];     // gate rows
  __shared__ float sred[TPB];
  __shared__ int   sidx[TPB];
  __shared__ float sgx[3*HPC];
  __shared__ unsigned s_eb[2];
  __shared__ int   s_topi[KTOP];
  __shared__ int   s_sel;
  __shared__ float s_sign;
  __shared__ float s_gm, s_iz;

  const int tid = threadIdx.x, lane = tid & 31, warp = tid >> 5;
  const int c = blockIdx.x;
  const int base = c * RPC;
  const int myRows = min(RPC, V - base);

  if (tid == 0){ s_eb[0] = 0; s_eb[1] = *(volatile unsigned*)&g_release; }

  // ---------- prologue ----------
  for (int i = tid; i < myRows; i += TPB) sb[i] = fcb[base + i];
  for (int v = c*TPB + tid; v < V; v += NB*TPB) g_hist[v] = masking[v];
  if (c < NGRU){
    for (int idx = tid; idx < 3*HPC*H; idx += TPB){
      int j = idx / H, col = idx % H;
      int a = j / 3, g = j % 3, h = c*HPC + a;
      float v0 = 0.f, v1 = 0.f;
      if (h < H){
        v0 = Wih[(size_t)(g*H + h)*H + col];
        v1 = Wih[(size_t)3*H*H + (size_t)(g*H + h)*H + col];
      }
      w0[idx] = v0; w1[idx] = v1;
    }
    for (int idx = tid; idx < HPC*H; idx += TPB){
      int a = idx / H, col = idx % H, h = c*HPC + a;
      wg[idx] = (h < H) ? fgcW[(size_t)h*H + col] : 0.f;
    }
  }
  // proc rows: CTA c handles rows r = c, c+NB, ...
  for (int r = c; r < H; r += NB){
    const float4* m4 = (const float4*)mem;
    const float4* w4 = (const float4*)(memW + (size_t)r*V);
    float s = 0.f;
    for (int i = tid; i < V/4; i += TPB){
      float4 a = m4[i], b = __ldcs(&w4[i]);
      s += a.x*b.x + a.y*b.y + a.z*b.z + a.w*b.w;
    }
    sred[tid] = s; __syncthreads();
    for (int st=256; st; st>>=1){ if (tid<st) sred[tid]+=sred[tid+st]; __syncthreads(); }
    if (tid == 0) g_proc[r] = tanhf(sred[0]);
    __syncthreads();
  }
  gsync(s_eb);

  // gbias for owned h's; CTA0 seeds x = emb_table[0]
  if (c < NGRU && warp < HPC){
    int h = c*HPC + warp;
    if (h < H){
      const float4* wr = (const float4*)(fgmW + (size_t)h*H);
      const float4* pr = (const float4*)g_proc;
      float4 wv = wr[lane],    pv = pr[lane];
      float s  = wv.x*pv.x + wv.y*pv.y + wv.z*pv.z + wv.w*pv.w;
      wv = wr[lane+32]; pv = pr[lane+32];
      s += wv.x*pv.x + wv.y*pv.y + wv.z*pv.z + wv.w*pv.w;
      #pragma unroll
      for (int off=16; off; off>>=1) s += __shfl_down_sync(0xffffffffu, s, off);
      if (lane == 0) g_gbias[h] = -(s + fgmb[h]);
    }
  }
  if (c == 0 && tid < H) g_xa[tid] = emb[tid];
  gsync(s_eb);

  // GRU for cell_0
  if (c < NGRU) gru_layer(w0, g_xa, g_xb, bih,       bhh,       c, scell, sgx);
  gsync(s_eb);
  if (c < NGRU) gru_layer(w1, g_xb, g_xc, bih + 3*H, bhh + 3*H, c, scell, sgx);
  gsync(s_eb);
  if (c < NGRU){
    if (tid < H) scell[tid] = __ldcg(&g_xc[tid]);
    __syncthreads();
    if (warp < HPC){
      int h = c*HPC + warp;
      float s = 0.f;
      if (h < H){
        const float4* wr = (const float4*)(wg + warp*H);
        const float4* xr = (const float4*)scell;
        float4 wv = wr[lane],    xv = xr[lane];
        s  = wv.x*xv.x + wv.y*xv.y + wv.z*xv.z + wv.w*xv.w;
        wv = wr[lane+32]; xv = xr[lane+32];
        s += wv.x*xv.x + wv.y*xv.y + wv.z*xv.z + wv.w*xv.w;
      }
      #pragma unroll
      for (int off=16; off; off>>=1) s += __shfl_down_sync(0xffffffffu, s, off);
      if (lane == 0) sgx[warp] = s;
    }
    __syncthreads();
    if (tid < HPC){
      int h = c*HPC + tid;
      if (h < H){
        float gate = sigmoidf_(g_gbias[h] + sgx[tid]);
        g_cell[h] = gate*g_proc[h] + (1.f-gate)*scell[h];
      }
    }
  }
  gsync(s_eb);

  // ---------- main loop ----------
  for (int t = 0; t < T_STEPS; t++){
    const int par = t & 1;

    // ===== phase L (all CTAs) =====
    if (tid == 0){ s_gm = __ldcg(&g_gmax[par^1]); s_iz = __ldcg(&g_invZ[par^1]); }
    if (tid < H) scell[tid] = __ldcg(&g_cell[tid]);
    __syncthreads();
    if (t > 0){
      for (int i = tid; i < myRows; i += TPB){
        int v = base + i;
        __stcs(&out[(size_t)(t-1)*V + v], expf(g_logits[par^1][v] - s_gm) * s_iz);
      }
    }
    {
      const float4* sc4 = (const float4*)scell;
      float4 c0 = sc4[lane], c1 = sc4[lane+32];
      for (int r = warp; r < myRows; r += TPB/32){
        int v = base + r;
        const float4* wr = (const float4*)(fcW + (size_t)v*H);
        float4 a = __ldcs(wr + lane), b = __ldcs(wr + lane + 32);
        float s = a.x*c0.x + a.y*c0.y + a.z*c0.z + a.w*c0.w
                + b.x*c1.x + b.y*c1.y + b.z*c1.z + b.w*c1.w;
        #pragma unroll
        for (int off=16; off; off>>=1) s += __shfl_down_sync(0xffffffffu, s, off);
        if (lane == 0){
          float lg = s + sb[r];
          slog[r] = lg;
          g_logits[par][v] = lg;
        }
      }
    }
    __syncthreads();
    // block max
    {
      float m = -CUDART_INF_F;
      for (int i = tid; i < myRows; i += TPB) m = fmaxf(m, slog[i]);
      sred[tid] = m; __syncthreads();
      for (int st=256; st; st>>=1){ if (tid<st) sred[tid]=fmaxf(sred[tid],sred[tid+st]); __syncthreads(); }
    }
    float bmax = sred[0];
    __syncthreads();
    // block expsum
    {
      float z = 0.f;
      for (int i = tid; i < myRows; i += TPB) z += expf(slog[i] - bmax);
      sred[tid] = z; __syncthreads();
      for (int st=256; st; st>>=1){ if (tid<st) sred[tid]+=sred[tid+st]; __syncthreads(); }
      if (tid == 0){ g_blkmax[c] = bmax; g_blksum[c] = sred[0]; }
    }
    __syncthreads();
    // mask in place
    for (int i = tid; i < myRows; i += TPB)
      if (__ldcg(&g_hist[base + i]) == 0.f) slog[i] = -CUDART_INF_F;
    __syncthreads();
    // block top-10 extraction
    for (int it = 0; it < KTOP; it++){
      float bv = -CUDART_INF_F; int bi_ = 0x7FFFFFFF;
      for (int i = tid; i < myRows; i += TPB){
        float vv = slog[i];
        if (vv > bv || (vv == bv && i < bi_)){ bv = vv; bi_ = i; }
      }
      sred[tid] = bv; sidx[tid] = bi_; __syncthreads();
      for (int st=256; st; st>>=1){
        if (tid < st){
          float ov = sred[tid+st]; int oi = sidx[tid+st];
          if (ov > sred[tid] || (ov == sred[tid] && oi < sidx[tid])){ sred[tid]=ov; sidx[tid]=oi; }
        }
        __syncthreads();
      }
      if (tid == 0){
        g_candv[c*KTOP + it] = sred[0];
        g_candi[c*KTOP + it] = base + sidx[0];
        slog[sidx[0]] = -CUDART_INF_F;
      }
      __syncthreads();
    }
    gsync(s_eb);   // S1

    // ===== SEL (CTA0) =====
    if (c == 0){
      // global max / Z
      float m = -CUDART_INF_F;
      for (int i = tid; i < NB; i += TPB) m = fmaxf(m, __ldcg(&g_blkmax[i]));
      sred[tid] = m; __syncthreads();
      for (int st=256; st; st>>=1){ if (tid<st) sred[tid]=fmaxf(sred[tid],sred[tid+st]); __syncthreads(); }
      float gmax = sred[0]; __syncthreads();
      float z = 0.f;
      for (int i = tid; i < NB; i += TPB)
        z += __ldcg(&g_blksum[i]) * expf(__ldcg(&g_blkmax[i]) - gmax);
      sred[tid] = z; __syncthreads();
      for (int st=256; st; st>>=1){ if (tid<st) sred[tid]+=sred[tid+st]; __syncthreads(); }
      if (tid == 0){ g_gmax[par] = gmax; g_invZ[par] = 1.f/sred[0]; }
      __syncthreads();
      // value[t]
      {
        float pv = 0.f;
        if (tid < H) pv = valW[tid] * __ldcg(&g_cell[tid]);
        sred[tid] = pv; __syncthreads();
        for (int st=256; st; st>>=1){ if (tid<st) sred[tid]+=sred[tid+st]; __syncthreads(); }
        if (tid == 0) out[OUT_VAL + t] = sred[0] + valb[0];
      }
      __syncthreads();
      // merge 1200 candidates -> top-10 (pos tie-break == index tie-break)
      for (int it = 0; it < KTOP; it++){
        float bv = -CUDART_INF_F; int bp = 0x7FFFFFFF;
        for (int i = tid; i < NC; i += TPB){
          float vv = __ldcg(&g_candv[i]);
          if (vv > bv || (vv == bv && i < bp)){ bv = vv; bp = i; }
        }
        sred[tid] = bv; sidx[tid] = bp; __syncthreads();
        for (int st=256; st; st>>=1){
          if (tid < st){
            float ov = sred[tid+st]; int oi = sidx[tid+st];
            if (ov > sred[tid] || (ov == sred[tid] && oi < sidx[tid])){ sred[tid]=ov; sidx[tid]=oi; }
          }
          __syncthreads();
        }
        if (tid == 0){
          int p = sidx[0];
          s_topi[it] = __ldcg(&g_candi[p]);
          g_candv[p] = -CUDART_INF_F;
        }
        __syncthreads();
      }
      if (tid == 0){
        int first = -1;
        #pragma unroll
        for (int r = 0; r < KTOP; r++)
          if (first < 0 && interesting[s_topi[r]] > 0.f) first = r;
        int hit = (first >= 0);
        int sel = hit ? s_topi[first] : s_topi[0];
        out[OUT_SEL + t] = (float)sel;
        out[OUT_HIT + t] = hit ? 1.f : 0.f;
        if (hit){ float hv = __ldcg(&g_hist[sel]); g_hist[sel] = hv - 1.f; }
        s_sel = sel; s_sign = hit ? 1.f : -1.f;
      }
      __syncthreads();
      if (tid < H) g_xa[tid] = s_sign * emb[(size_t)s_sel*H + tid];
    }
    gsync(s_eb);   // S2

    // ===== GRU L0 =====
    if (c < NGRU) gru_layer(w0, g_xa, g_xb, bih,       bhh,       c, scell, sgx);
    gsync(s_eb);   // S3
    // ===== GRU L1 =====
    if (c < NGRU) gru_layer(w1, g_xb, g_xc, bih + 3*H, bhh + 3*H, c, scell, sgx);
    gsync(s_eb);   // S4
    // ===== gate + cell =====
    if (c < NGRU){
      if (tid < H) scell[tid] = __ldcg(&g_xc[tid]);
      __syncthreads();
      if (warp < HPC){
        int h = c*HPC + warp;
        float s = 0.f;
        if (h < H){
          const float4* wr = (const float4*)(wg + warp*H);
          const float4* xr = (const float4*)scell;
          float4 wv = wr[lane],    xv = xr[lane];
          s  = wv.x*xv.x + wv.y*xv.y + wv.z*xv.z + wv.w*xv.w;
          wv = wr[lane+32]; xv = xr[lane+32];
          s += wv.x*xv.x + wv.y*xv.y + wv.z*xv.z + wv.w*xv.w;
        }
        #pragma unroll
        for (int off=16; off; off>>=1) s += __shfl_down_sync(0xffffffffu, s, off);
        if (lane == 0) sgx[warp] = s;
      }
      __syncthreads();
      if (tid < HPC){
        int h = c*HPC + tid;
        if (h < H){
          float gate = sigmoidf_(g_gbias[h] + sgx[tid]);
          g_cell[h] = gate*g_proc[h] + (1.f-gate)*scell[h];
        }
      }
    }
    gsync(s_eb);   // S5
  }

  // ---------- epilogue ----------
  {
    const int par = (T_STEPS-1) & 1;
    if (tid == 0){ s_gm = __ldcg(&g_gmax[par]); s_iz = __ldcg(&g_invZ[par]); }
    __syncthreads();
    for (int i = tid; i < myRows; i += TPB){
      int v = base + i;
      __stcs(&out[(size_t)(T_STEPS-1)*V + v], expf(g_logits[par][v] - s_gm) * s_iz);
    }
    for (int v = c*TPB + tid; v < V; v += NB*TPB)
      __stcs(&out[OUT_HIST + v], __ldcg(&g_hist[v]));
  }
}

extern "C" void kernel_launch(void* const* d_in, const int* in_sizes, int n_in,
                              void* d_out, int out_size){
  (void)in_sizes; (void)n_in; (void)out_size;
  const float* interesting = (const float*)d_in[0];
  const float* masking     = (const float*)d_in[1];
  const float* mem         = (const float*)d_in[2];
  const float* emb         = (const float*)d_in[3];
  const float* Wih         = (const float*)d_in[4];
  /* d_in[5] = gru_Whh unused (hidden state always zero) */
  const float* bih         = (const float*)d_in[6];
  const float* bhh         = (const float*)d_in[7];
  const float* fcW         = (const float*)d_in[8];
  const float* fcb         = (const float*)d_in[9];
  const float* valW        = (const float*)d_in[10];
  const float* valb        = (const float*)d_in[11];
  const float* memW        = (const float*)d_in[12];
  const float* fgmW        = (const float*)d_in[13];
  const float* fgmb        = (const float*)d_in[14];
  const float* fgcW        = (const float*)d_in[15];
  float* out = (float*)d_out;

  k_persist<<<NB, TPB>>>(interesting, masking, mem, emb, Wih, bih, bhh,
                         fcW, fcb, valW, valb, memW, fgmW, fgmb, fgcW, out);
}

// round 5
// speedup vs baseline: 3.3433x; 2.0360x over previous
#include <cuda_runtime.h>
#include <math_constants.h>

#define V 100000
#define H 256
#define T_STEPS 64
#define NB 148
#define TPB 512
#define NWARP (TPB/32)        /* 16 */
#define RPC 676               /* ceil(V/NB): 148*676 = 100048 */
#define KTOP 10
#define HPC 3
#define NGRU 86               /* ceil(H/HPC) */

#define OUT_SEL   ((size_t)T_STEPS * V)
#define OUT_VAL   (OUT_SEL + T_STEPS)
#define OUT_HIT   (OUT_VAL + T_STEPS)
#define OUT_HIST  (OUT_HIT + T_STEPS)

// ---------------- device scratch ----------------
__device__ __align__(16) float g_cell[H];
__device__ __align__(16) float g_proc[H];
__device__ __align__(16) float g_gbias[H];
__device__ __align__(16) float g_xa[H];
__device__ __align__(16) float g_xb[H];
__device__ __align__(16) float g_xc[H];
__device__ float g_blkmax[NB];
__device__ float g_blksum[NB];
__device__ float g_candv[NB*KTOP];
__device__ int   g_candi[NB*KTOP];
__device__ float g_gmaxS, g_invZS;
__device__ int   g_last_sel, g_last_hit;
__device__ unsigned g_arrive[NB];   // zero-init
__device__ unsigned g_releaseF;     // monotonic across launches

__device__ __forceinline__ float sigmoidf_(float x){ return 1.f/(1.f+expf(-x)); }
__device__ __forceinline__ float dot8(float4 a, float4 b, float4 x, float4 y){
  return a.x*x.x + a.y*x.y + a.z*x.z + a.w*x.w
       + b.x*y.x + b.y*y.y + b.z*y.z + b.w*y.w;
}

// flag-array grid barrier: 1 store per CTA, CTA0 polls flags, single release store
__device__ __forceinline__ void gsync(unsigned* s_eb, int c){
  __syncthreads();
  if (threadIdx.x == 0){
    unsigned e = s_eb[0] + 1; s_eb[0] = e;
    __threadfence();
    *(volatile unsigned*)&g_arrive[c] = s_eb[1] + e;
  }
  __syncthreads();
  if (c == 0){
    unsigned e = s_eb[0];
    if (threadIdx.x < NB){
      while (*(volatile unsigned*)&g_arrive[threadIdx.x] - s_eb[1] < e) { }
    }
    __syncthreads();
    if (threadIdx.x == 0){
      __threadfence();
      *(volatile unsigned*)&g_releaseF = s_eb[1] + e;
    }
  } else {
    if (threadIdx.x == 0){
      unsigned e = s_eb[0];
      while (*(volatile unsigned*)&g_releaseF - s_eb[1] < e) { }
      __threadfence();
    }
  }
  __syncthreads();
}

// shfl block reductions (2 syncthreads each, trailing sync protects buffer reuse)
__device__ __forceinline__ float blockMaxB(float v, float* sw){
  int lane = threadIdx.x & 31, warp = threadIdx.x >> 5;
  #pragma unroll
  for (int o=16; o; o>>=1) v = fmaxf(v, __shfl_down_sync(0xffffffffu, v, o));
  if (lane == 0) sw[warp] = v;
  __syncthreads();
  if (warp == 0){
    float x = (lane < NWARP) ? sw[lane] : -CUDART_INF_F;
    #pragma unroll
    for (int o=8; o; o>>=1) x = fmaxf(x, __shfl_down_sync(0xffffffffu, x, o));
    if (lane == 0) sw[0] = x;
  }
  __syncthreads();
  float r = sw[0];
  __syncthreads();
  return r;
}
__device__ __forceinline__ float blockSumB(float v, float* sw){
  int lane = threadIdx.x & 31, warp = threadIdx.x >> 5;
  #pragma unroll
  for (int o=16; o; o>>=1) v += __shfl_down_sync(0xffffffffu, v, o);
  if (lane == 0) sw[warp] = v;
  __syncthreads();
  if (warp == 0){
    float x = (lane < NWARP) ? sw[lane] : 0.f;
    #pragma unroll
    for (int o=8; o; o>>=1) x += __shfl_down_sync(0xffffffffu, x, o);
    if (lane == 0) sw[0] = x;
  }
  __syncthreads();
  float r = sw[0];
  __syncthreads();
  return r;
}
// block argmax (value desc, index asc tiebreak); returns winner in v,i for all threads
__device__ __forceinline__ void bargmax(float &v, int &i, float* swv, int* swi){
  int lane = threadIdx.x & 31, warp = threadIdx.x >> 5;
  #pragma unroll
  for (int o=16; o; o>>=1){
    float ov = __shfl_down_sync(0xffffffffu, v, o);
    int   oi = __shfl_down_sync(0xffffffffu, i, o);
    if (ov > v || (ov == v && oi < i)){ v = ov; i = oi; }
  }
  if (lane == 0){ swv[warp] = v; swi[warp] = i; }
  __syncthreads();
  if (warp == 0){
    float x = (lane < NWARP) ? swv[lane] : -CUDART_INF_F;
    int  xi = (lane < NWARP) ? swi[lane] : 0x7FFFFFFF;
    #pragma unroll
    for (int o=8; o; o>>=1){
      float ov = __shfl_down_sync(0xffffffffu, x, o);
      int   oi = __shfl_down_sync(0xffffffffu, xi, o);
      if (ov > x || (ov == x && oi < xi)){ x = ov; xi = oi; }
    }
    if (lane == 0){ swv[0] = x; swi[0] = xi; }
  }
  __syncthreads();
  v = swv[0]; i = swi[0];
  __syncthreads();
}

// one GRU layer for this CTA's owned h's (weights in smem, x via global)
__device__ __forceinline__ void gru_layer(const float* Wsm, const float* xin_g,
                                          float* xout_g, const float* bi,
                                          const float* bh, int c,
                                          float* sx, float* sgx){
  int tid = threadIdx.x, lane = tid & 31, warp = tid >> 5;
  if (tid < H) sx[tid] = __ldcg(&xin_g[tid]);
  __syncthreads();
  if (warp < 3*HPC){
    int a = warp / 3;
    int h = c*HPC + a;
    float s = 0.f;
    if (h < H){
      const float4* wr = (const float4*)(Wsm + warp*H);
      const float4* xr = (const float4*)sx;
      s = dot8(wr[lane], wr[lane+32], xr[lane], xr[lane+32]);
    }
    #pragma unroll
    for (int o=16; o; o>>=1) s += __shfl_down_sync(0xffffffffu, s, o);
    if (lane == 0) sgx[warp] = s;
  }
  __syncthreads();
  if (tid < HPC){
    int h = c*HPC + tid;
    if (h < H){
      float r = sigmoidf_(sgx[tid*3+0] + bi[h]     + bh[h]);
      float z = sigmoidf_(sgx[tid*3+1] + bi[H+h]   + bh[H+h]);
      float n = tanhf   (sgx[tid*3+2] + bi[2*H+h] + r*bh[2*H+h]);
      xout_g[h] = (1.f - z) * n;
    }
  }
}

__global__ __launch_bounds__(TPB, 1)
void k_persist(const float* __restrict__ interesting, const float* __restrict__ masking,
               const float* __restrict__ mem, const float* __restrict__ emb,
               const float* __restrict__ Wih, const float* __restrict__ bih,
               const float* __restrict__ bhh, const float* __restrict__ fcW,
               const float* __restrict__ fcb, const float* __restrict__ valW,
               const float* __restrict__ valb, const float* __restrict__ memW,
               const float* __restrict__ fgmW, const float* __restrict__ fgmb,
               const float* __restrict__ fgcW, float* __restrict__ out){
  __shared__ __align__(16) float scell[H];
  __shared__ float sb[RPC];
  __shared__ float slogit[RPC];      // raw logits, persist across phases/steps
  __shared__ float s_hist[RPC];      // hist slice, persists whole kernel
  __shared__ __align__(16) float w0[3*HPC*H];
  __shared__ __align__(16) float w1[3*HPC*H];
  __shared__ __align__(16) float wg[HPC*H];
  __shared__ float swv[NWARP];
  __shared__ int   swi[NWARP];
  __shared__ int   swc[NWARP];
  __shared__ float sgx[3*HPC];
  __shared__ int   sptr[NB];
  __shared__ unsigned s_eb[2];
  __shared__ int   s_topi[KTOP];
  __shared__ int   s_sel;
  __shared__ float s_sign, s_gm, s_iz;

  const int tid = threadIdx.x, lane = tid & 31, warp = tid >> 5;
  const int c = blockIdx.x;
  const int base = c * RPC;
  const int myRows = min(RPC, V - base);

  if (tid == 0){ s_eb[0] = 0; s_eb[1] = *(volatile unsigned*)&g_releaseF; }

  // ---------- prologue ----------
  for (int i = tid; i < myRows; i += TPB){
    sb[i] = fcb[base + i];
    s_hist[i] = masking[base + i];
  }
  if (c < NGRU){
    for (int idx = tid; idx < 3*HPC*H; idx += TPB){
      int j = idx / H, col = idx % H;
      int a = j / 3, g = j % 3, h = c*HPC + a;
      float v0 = 0.f, v1 = 0.f;
      if (h < H){
        v0 = Wih[(size_t)(g*H + h)*H + col];
        v1 = Wih[(size_t)3*H*H + (size_t)(g*H + h)*H + col];
      }
      w0[idx] = v0; w1[idx] = v1;
    }
    for (int idx = tid; idx < HPC*H; idx += TPB){
      int a = idx / H, col = idx % H, h = c*HPC + a;
      wg[idx] = (h < H) ? fgcW[(size_t)h*H + col] : 0.f;
    }
  }
  // proc rows: CTA c handles rows r = c, c+NB, ... (streaming reads: single-use)
  for (int r = c; r < H; r += NB){
    const float4* m4 = (const float4*)mem;
    const float4* w4 = (const float4*)(memW + (size_t)r*V);
    float s = 0.f;
    for (int i = tid; i < V/4; i += TPB){
      float4 a = m4[i], b = __ldcs(&w4[i]);
      s += a.x*b.x + a.y*b.y + a.z*b.z + a.w*b.w;
    }
    s = blockSumB(s, swv);
    if (tid == 0) g_proc[r] = tanhf(s);
  }
  gsync(s_eb, c);

  // gbias for owned h's; CTA0 seeds x = emb_table[0]
  if (c < NGRU && warp < HPC){
    int h = c*HPC + warp;
    if (h < H){
      const float4* wr = (const float4*)(fgmW + (size_t)h*H);
      const float4* pr = (const float4*)g_proc;
      float s = dot8(wr[lane], wr[lane+32], pr[lane], pr[lane+32]);
      #pragma unroll
      for (int o=16; o; o>>=1) s += __shfl_down_sync(0xffffffffu, s, o);
      if (lane == 0) g_gbias[h] = -(s + fgmb[h]);
    }
  }
  if (c == 0 && tid < H) g_xa[tid] = emb[tid];
  gsync(s_eb, c);

  // GRU for cell_0
  if (c < NGRU) gru_layer(w0, g_xa, g_xb, bih,       bhh,       c, scell, sgx);
  gsync(s_eb, c);
  if (c < NGRU) gru_layer(w1, g_xb, g_xc, bih + 3*H, bhh + 3*H, c, scell, sgx);
  gsync(s_eb, c);
  if (c < NGRU){
    if (tid < H) scell[tid] = __ldcg(&g_xc[tid]);
    __syncthreads();
    if (warp < HPC){
      int h = c*HPC + warp;
      float s = 0.f;
      if (h < H){
        const float4* wr = (const float4*)(wg + warp*H);
        const float4* xr = (const float4*)scell;
        s = dot8(wr[lane], wr[lane+32], xr[lane], xr[lane+32]);
      }
      #pragma unroll
      for (int o=16; o; o>>=1) s += __shfl_down_sync(0xffffffffu, s, o);
      if (lane == 0) sgx[warp] = s;
    }
    __syncthreads();
    if (tid < HPC){
      int h = c*HPC + tid;
      if (h < H){
        float gate = sigmoidf_(g_gbias[h] + sgx[tid]);
        g_cell[h] = gate*g_proc[h] + (1.f-gate)*scell[h];
      }
    }
  }
  gsync(s_eb, c);

  // ---------- main loop ----------
  for (int t = 0; t < T_STEPS; t++){
    // ===== phase L (all CTAs) =====
    if (tid == 0 && t > 0){
      s_gm = __ldcg(&g_gmaxS); s_iz = __ldcg(&g_invZS);
      int hs = __ldcg(&g_last_hit), sl = __ldcg(&g_last_sel);
      if (hs && sl >= base && sl < base + myRows) s_hist[sl - base] -= 1.f;
    }
    if (tid < H) scell[tid] = __ldcg(&g_cell[tid]);
    __syncthreads();
    if (t > 0){
      float gm = s_gm, iz = s_iz;
      for (int i = tid; i < myRows; i += TPB)
        __stcs(&out[(size_t)(t-1)*V + base + i], expf(slogit[i]-gm)*iz);
      __syncthreads();
    }
    // logits matvec: warp-per-row, 4 rows in flight (default caching -> L2 resident)
    {
      const float4* sc4 = (const float4*)scell;
      float4 c0 = sc4[lane], c1 = sc4[lane+32];
      for (int r = warp; r < myRows; r += NWARP*4){
        int r1 = r + NWARP, r2 = r + 2*NWARP, r3 = r + 3*NWARP;
        int q1 = min(r1, myRows-1), q2 = min(r2, myRows-1), q3 = min(r3, myRows-1);
        const float4* p0 = (const float4*)(fcW + (size_t)(base + r )*H);
        const float4* p1 = (const float4*)(fcW + (size_t)(base + q1)*H);
        const float4* p2 = (const float4*)(fcW + (size_t)(base + q2)*H);
        const float4* p3 = (const float4*)(fcW + (size_t)(base + q3)*H);
        float4 a0 = p0[lane], b0 = p0[lane+32];
        float4 a1 = p1[lane], b1 = p1[lane+32];
        float4 a2 = p2[lane], b2 = p2[lane+32];
        float4 a3 = p3[lane], b3 = p3[lane+32];
        float s0 = dot8(a0,b0,c0,c1);
        float s1 = dot8(a1,b1,c0,c1);
        float s2 = dot8(a2,b2,c0,c1);
        float s3 = dot8(a3,b3,c0,c1);
        #pragma unroll
        for (int o=16; o; o>>=1){
          s0 += __shfl_down_sync(0xffffffffu, s0, o);
          s1 += __shfl_down_sync(0xffffffffu, s1, o);
          s2 += __shfl_down_sync(0xffffffffu, s2, o);
          s3 += __shfl_down_sync(0xffffffffu, s3, o);
        }
        if (lane == 0){
          slogit[r] = s0 + sb[r];
          if (r1 < myRows) slogit[r1] = s1 + sb[r1];
          if (r2 < myRows) slogit[r2] = s2 + sb[r2];
          if (r3 < myRows) slogit[r3] = s3 + sb[r3];
        }
      }
    }
    __syncthreads();
    // block softmax stats (shfl reductions)
    {
      float v0 = (tid      < myRows) ? slogit[tid]      : -CUDART_INF_F;
      float v1 = (tid+TPB  < myRows) ? slogit[tid+TPB]  : -CUDART_INF_F;
      float m  = blockMaxB(fmaxf(v0, v1), swv);
      float z  = 0.f;
      if (tid     < myRows) z += expf(v0 - m);
      if (tid+TPB < myRows) z += expf(v1 - m);
      z = blockSumB(z, swv);
      if (tid == 0){ g_blkmax[c] = m; g_blksum[c] = z; }
    }
    // block top-10: per-thread sorted 2-element heads + 10 tournament rounds
    {
      float h0v = -CUDART_INF_F, h1v = -CUDART_INF_F;
      int   h0i = 0x7FFFFFFF,    h1i = 0x7FFFFFFF;
      if (tid < myRows && s_hist[tid] != 0.f){ h0v = slogit[tid]; h0i = tid; }
      if (tid+TPB < myRows && s_hist[tid+TPB] != 0.f){
        float vv = slogit[tid+TPB]; int ii = tid+TPB;
        if (vv > h0v){ h1v = h0v; h1i = h0i; h0v = vv; h0i = ii; }
        else         { h1v = vv;  h1i = ii; }
      }
      for (int it = 0; it < KTOP; it++){
        float bv = h0v; int bi_ = h0i;
        bargmax(bv, bi_, swv, swi);
        if (tid == 0){
          g_candv[c*KTOP + it] = bv;
          g_candi[c*KTOP + it] = (bi_ == 0x7FFFFFFF) ? 0x7FFFFFFF : base + bi_;
        }
        if (h0i == bi_){ h0v = h1v; h0i = h1i; h1v = -CUDART_INF_F; h1i = 0x7FFFFFFF; }
      }
    }
    gsync(s_eb, c);   // S1

    // ===== SEL (CTA0) =====
    if (c == 0){
      float bm = (tid < NB) ? __ldcg(&g_blkmax[tid]) : -CUDART_INF_F;
      float gmax = blockMaxB(bm, swv);
      float zz = (tid < NB) ? __ldcg(&g_blksum[tid]) * expf(bm - gmax) : 0.f;
      float Z = blockSumB(zz, swv);
      if (tid == 0){ g_gmaxS = gmax; g_invZS = 1.f/Z; }
      // value[t]
      float pv = (tid < H) ? valW[tid] * __ldcg(&g_cell[tid]) : 0.f;
      pv = blockSumB(pv, swv);
      if (tid == 0) out[OUT_VAL + t] = pv + valb[0];
      // global top-10: 148-way sorted-heads tournament
      if (tid < NB) sptr[tid] = 0;
      __syncthreads();
      for (int it = 0; it < KTOP; it++){
        float v = -CUDART_INF_F; int ci = 0x7FFFFFFF; int cta = -1;
        if (tid < NB){
          int p = sptr[tid];
          v  = __ldcg(&g_candv[tid*KTOP + p]);
          ci = __ldcg(&g_candi[tid*KTOP + p]);
          cta = tid;
        }
        #pragma unroll
        for (int o=16; o; o>>=1){
          float ov = __shfl_down_sync(0xffffffffu, v, o);
          int   oi = __shfl_down_sync(0xffffffffu, ci, o);
          int   oc = __shfl_down_sync(0xffffffffu, cta, o);
          if (ov > v || (ov == v && oi < ci)){ v = ov; ci = oi; cta = oc; }
        }
        if (lane == 0){ swv[warp] = v; swi[warp] = ci; swc[warp] = cta; }
        __syncthreads();
        if (tid == 0){
          float bv = swv[0]; int bci = swi[0]; int bc = swc[0];
          #pragma unroll
          for (int w = 1; w < (NB+31)/32; w++){
            if (swv[w] > bv || (swv[w] == bv && swi[w] < bci)){
              bv = swv[w]; bci = swi[w]; bc = swc[w];
            }
          }
          s_topi[it] = bci;
          sptr[bc]++;
        }
        __syncthreads();
      }
      if (tid == 0){
        int first = -1;
        #pragma unroll
        for (int r = 0; r < KTOP; r++)
          if (first < 0 && interesting[s_topi[r]] > 0.f) first = r;
        int hit = (first >= 0);
        int sel = hit ? s_topi[first] : s_topi[0];
        out[OUT_SEL + t] = (float)sel;
        out[OUT_HIT + t] = hit ? 1.f : 0.f;
        g_last_sel = sel; g_last_hit = hit;
        s_sel = sel; s_sign = hit ? 1.f : -1.f;
      }
      __syncthreads();
      if (tid < H) g_xa[tid] = s_sign * emb[(size_t)s_sel*H + tid];
    }
    gsync(s_eb, c);   // S2

    // ===== GRU L0 / L1 / gate =====
    if (c < NGRU) gru_layer(w0, g_xa, g_xb, bih,       bhh,       c, scell, sgx);
    gsync(s_eb, c);   // S3
    if (c < NGRU) gru_layer(w1, g_xb, g_xc, bih + 3*H, bhh + 3*H, c, scell, sgx);
    gsync(s_eb, c);   // S4
    if (c < NGRU){
      if (tid < H) scell[tid] = __ldcg(&g_xc[tid]);
      __syncthreads();
      if (warp < HPC){
        int h = c*HPC + warp;
        float s = 0.f;
        if (h < H){
          const float4* wr = (const float4*)(wg + warp*H);
          const float4* xr = (const float4*)scell;
          s = dot8(wr[lane], wr[lane+32], xr[lane], xr[lane+32]);
        }
        #pragma unroll
        for (int o=16; o; o>>=1) s += __shfl_down_sync(0xffffffffu, s, o);
        if (lane == 0) sgx[warp] = s;
      }
      __syncthreads();
      if (tid < HPC){
        int h = c*HPC + tid;
        if (h < H){
          float gate = sigmoidf_(g_gbias[h] + sgx[tid]);
          g_cell[h] = gate*g_proc[h] + (1.f-gate)*scell[h];
        }
      }
    }
    gsync(s_eb, c);   // S5
  }

  // ---------- epilogue ----------
  if (tid == 0){
    s_gm = __ldcg(&g_gmaxS); s_iz = __ldcg(&g_invZS);
    int hs = __ldcg(&g_last_hit), sl = __ldcg(&g_last_sel);
    if (hs && sl >= base && sl < base + myRows) s_hist[sl - base] -= 1.f;
  }
  __syncthreads();
  {
    float gm = s_gm, iz = s_iz;
    for (int i = tid; i < myRows; i += TPB){
      __stcs(&out[(size_t)(T_STEPS-1)*V + base + i], expf(slogit[i]-gm)*iz);
      __stcs(&out[OUT_HIST + base + i], s_hist[i]);
    }
  }
}

extern "C" void kernel_launch(void* const* d_in, const int* in_sizes, int n_in,
                              void* d_out, int out_size){
  (void)in_sizes; (void)n_in; (void)out_size;
  const float* interesting = (const float*)d_in[0];
  const float* masking     = (const float*)d_in[1];
  const float* mem         = (const float*)d_in[2];
  const float* emb         = (const float*)d_in[3];
  const float* Wih         = (const float*)d_in[4];
  /* d_in[5] = gru_Whh unused (hidden state always zero) */
  const float* bih         = (const float*)d_in[6];
  const float* bhh         = (const float*)d_in[7];
  const float* fcW         = (const float*)d_in[8];
  const float* fcb         = (const float*)d_in[9];
  const float* valW        = (const float*)d_in[10];
  const float* valb        = (const float*)d_in[11];
  const float* memW        = (const float*)d_in[12];
  const float* fgmW        = (const float*)d_in[13];
  const float* fgmb        = (const float*)d_in[14];
  const float* fgcW        = (const float*)d_in[15];
  float* out = (float*)d_out;

  k_persist<<<NB, TPB>>>(interesting, masking, mem, emb, Wih, bih, bhh,
                         fcW, fcb, valW, valb, memW, fgmW, fgmb, fgcW, out);
}

// round 6
// speedup vs baseline: 3.4062x; 1.0188x over previous
#include <cuda_runtime.h>
#include <math_constants.h>

#define V 100000
#define H 256
#define T_STEPS 64
#define NB 148
#define TPB 512
#define NWARP 16
#define RPC 676               /* 148*676 = 100048 >= V */
#define KTOP 10
#define NCAND (NB*KTOP)       /* 1480 */
#define HPC 3
#define NGRU 86

#define OUT_SEL   ((size_t)T_STEPS * V)
#define OUT_VAL   (OUT_SEL + T_STEPS)
#define OUT_HIT   (OUT_VAL + T_STEPS)
#define OUT_HIST  (OUT_HIT + T_STEPS)

// ---------------- device scratch ----------------
__device__ __align__(16) float g_cell[H];
__device__ __align__(16) float g_proc[H];
__device__ __align__(16) float g_xb[H];
__device__ __align__(16) float g_xc[H];
__device__ float g_blkmax[NB];
__device__ float g_blksum[NB];
__device__ float g_candv[NCAND];
__device__ int   g_candi[NCAND];
__device__ int   g_candt[NCAND];
__device__ float g_gmaxS, g_invZS;
__device__ int   g_selP;            // (sel<<1)|hit
__device__ unsigned g_arr1[NB];
__device__ unsigned g_rel1;
__device__ unsigned g_arrG[NGRU];
__device__ unsigned g_relG;
__device__ unsigned g_arrC[NGRU];
__device__ unsigned g_relC;
__device__ unsigned g_selF;

__device__ __forceinline__ float sigmoidf_(float x){ return 1.f/(1.f+expf(-x)); }
__device__ __forceinline__ float dot8(float4 a, float4 b, float4 x, float4 y){
  return a.x*x.x + a.y*x.y + a.z*x.z + a.w*x.w
       + b.x*y.x + b.y*y.y + b.z*y.z + b.w*y.w;
}

// ---------------- reset: absolute epochs each launch ----------------
__global__ __launch_bounds__(TPB) void k_reset(){
  int i = threadIdx.x;
  if (i < NB)   g_arr1[i] = 0u;
  if (i < NGRU){ g_arrG[i] = 0u; g_arrC[i] = 0u; }
  if (i == 0){ g_rel1 = 0u; g_relG = 0u; g_relC = 0u; g_selF = 0u; }
}

// block reductions (shfl two-level)
__device__ __forceinline__ float blockMaxB(float v, float* sw){
  int lane = threadIdx.x & 31, warp = threadIdx.x >> 5;
  #pragma unroll
  for (int o=16; o; o>>=1) v = fmaxf(v, __shfl_down_sync(0xffffffffu, v, o));
  if (lane == 0) sw[warp] = v;
  __syncthreads();
  if (warp == 0){
    float x = (lane < NWARP) ? sw[lane] : -CUDART_INF_F;
    #pragma unroll
    for (int o=8; o; o>>=1) x = fmaxf(x, __shfl_down_sync(0xffffffffu, x, o));
    if (lane == 0) sw[0] = x;
  }
  __syncthreads();
  float r = sw[0];
  __syncthreads();
  return r;
}
__device__ __forceinline__ float blockSumB(float v, float* sw){
  int lane = threadIdx.x & 31, warp = threadIdx.x >> 5;
  #pragma unroll
  for (int o=16; o; o>>=1) v += __shfl_down_sync(0xffffffffu, v, o);
  if (lane == 0) sw[warp] = v;
  __syncthreads();
  if (warp == 0){
    float x = (lane < NWARP) ? sw[lane] : 0.f;
    #pragma unroll
    for (int o=8; o; o>>=1) x += __shfl_down_sync(0xffffffffu, x, o);
    if (lane == 0) sw[0] = x;
  }
  __syncthreads();
  float r = sw[0];
  __syncthreads();
  return r;
}
__device__ __forceinline__ void bargmax(float &v, int &i, float* swv, int* swi){
  int lane = threadIdx.x & 31, warp = threadIdx.x >> 5;
  #pragma unroll
  for (int o=16; o; o>>=1){
    float ov = __shfl_down_sync(0xffffffffu, v, o);
    int   oi = __shfl_down_sync(0xffffffffu, i, o);
    if (ov > v || (ov == v && oi < i)){ v = ov; i = oi; }
  }
  if (lane == 0){ swv[warp] = v; swi[warp] = i; }
  __syncthreads();
  if (warp == 0){
    float x = (lane < NWARP) ? swv[lane] : -CUDART_INF_F;
    int  xi = (lane < NWARP) ? swi[lane] : 0x7FFFFFFF;
    #pragma unroll
    for (int o=8; o; o>>=1){
      float ov = __shfl_down_sync(0xffffffffu, x, o);
      int   oi = __shfl_down_sync(0xffffffffu, xi, o);
      if (ov > x || (ov == x && oi < xi)){ x = ov; xi = oi; }
    }
    if (lane == 0){ swv[0] = x; swi[0] = xi; }
  }
  __syncthreads();
  v = swv[0]; i = swi[0];
  __syncthreads();
}

// GRU sub-barrier among NGRU CTAs, absolute epoch e
__device__ __forceinline__ void gru_barrier(int c, int tid, unsigned e){
  __syncthreads();
  if (tid == 0){ __threadfence(); *(volatile unsigned*)&g_arrG[c] = e; }
  if (c == 0){
    if (tid < NGRU){ while (*(volatile unsigned*)&g_arrG[tid] < e) {} }
    __syncthreads();
    if (tid == 0){ __threadfence(); *(volatile unsigned*)&g_relG = e; }
  } else {
    if (tid == 0){ while (*(volatile unsigned*)&g_relG < e) {} __threadfence(); }
  }
  __syncthreads();
}

// 9 warps: dots for 3 h x 3 gates from smem weights against smem x
__device__ __forceinline__ void gru_dots(const float* Wsm, const float* sx, float* sgx, int c){
  int tid = threadIdx.x, lane = tid & 31, warp = tid >> 5;
  if (warp < 3*HPC){
    int a = warp / 3;
    int h = c*HPC + a;
    float s = 0.f;
    if (h < H){
      const float4* wr = (const float4*)(Wsm + warp*H);
      const float4* xr = (const float4*)sx;
      s = dot8(wr[lane], wr[lane+32], xr[lane], xr[lane+32]);
    }
    #pragma unroll
    for (int o=16; o; o>>=1) s += __shfl_down_sync(0xffffffffu, s, o);
    if (lane == 0) sgx[warp] = s;
  }
  __syncthreads();
}
__device__ __forceinline__ void gru_act(const float* sgx, const float* sx,
                                        const float* bi, const float* bh,
                                        float* xout_g, int c){
  int tid = threadIdx.x;
  (void)sx;
  if (tid < HPC){
    int h = c*HPC + tid;
    if (h < H){
      float r = sigmoidf_(sgx[tid*3+0] + bi[h]     + bh[h]);
      float z = sigmoidf_(sgx[tid*3+1] + bi[H+h]   + bh[H+h]);
      float n = tanhf   (sgx[tid*3+2] + bi[2*H+h] + r*bh[2*H+h]);
      xout_g[h] = (1.f - z) * n;
    }
  }
}

__global__ __launch_bounds__(TPB, 1)
void k_persist(const float* __restrict__ interesting, const float* __restrict__ masking,
               const float* __restrict__ mem, const float* __restrict__ emb,
               const float* __restrict__ Wih, const float* __restrict__ bih,
               const float* __restrict__ bhh, const float* __restrict__ fcW,
               const float* __restrict__ fcb, const float* __restrict__ valW,
               const float* __restrict__ valb, const float* __restrict__ memW,
               const float* __restrict__ fgmW, const float* __restrict__ fgmb,
               const float* __restrict__ fgcW, float* __restrict__ out){
  __shared__ __align__(16) float scell[H];
  __shared__ __align__(16) float sx[H];
  __shared__ float sb[RPC];
  __shared__ float slogit[RPC];
  __shared__ float s_hist[RPC];
  __shared__ unsigned char s_int[RPC];
  __shared__ __align__(16) float w0[3*HPC*H];
  __shared__ __align__(16) float w1[3*HPC*H];
  __shared__ __align__(16) float wg[HPC*H];
  __shared__ float scv[NCAND];
  __shared__ int   sci[NCAND];
  __shared__ unsigned char sct[NCAND];
  __shared__ float swv[NWARP];
  __shared__ int   swi[NWARP];
  __shared__ int   swp[NWARP];
  __shared__ float sgx[3*HPC];
  __shared__ float sgbias[HPC];
  __shared__ float sprocL[HPC];
  __shared__ int   s_topi[KTOP];
  __shared__ unsigned char s_topt[KTOP];
  __shared__ float s_gm, s_iz, s_sign;
  __shared__ int   s_sel, s_hit;

  const int tid = threadIdx.x, lane = tid & 31, warp = tid >> 5;
  const int c = blockIdx.x;
  const int base = c * RPC;
  const int myRows = min(RPC, V - base);

  // ---------- prologue loads ----------
  for (int i = tid; i < myRows; i += TPB){
    sb[i] = fcb[base + i];
    s_hist[i] = masking[base + i];
    s_int[i] = (interesting[base + i] > 0.f) ? 1 : 0;
  }
  if (c < NGRU){
    for (int idx = tid; idx < 3*HPC*H; idx += TPB){
      int j = idx / H, col = idx % H;
      int a = j / 3, g = j % 3, h = c*HPC + a;
      float v0 = 0.f, v1 = 0.f;
      if (h < H){
        v0 = Wih[(size_t)(g*H + h)*H + col];
        v1 = Wih[(size_t)3*H*H + (size_t)(g*H + h)*H + col];
      }
      w0[idx] = v0; w1[idx] = v1;
    }
    for (int idx = tid; idx < HPC*H; idx += TPB){
      int a = idx / H, col = idx % H, h = c*HPC + a;
      wg[idx] = (h < H) ? fgcW[(size_t)h*H + col] : 0.f;
    }
  }
  // proc rows r=c, c+NB
  for (int r = c; r < H; r += NB){
    const float4* m4 = (const float4*)mem;
    const float4* w4 = (const float4*)(memW + (size_t)r*V);
    float s = 0.f;
    for (int i = tid; i < V/4; i += TPB){
      float4 a = m4[i], b = __ldcs(&w4[i]);
      s += a.x*b.x + a.y*b.y + a.z*b.z + a.w*b.w;
    }
    s = blockSumB(s, swv);
    if (tid == 0) g_proc[r] = tanhf(s);
  }

  // ---------- full barrier (epoch 1) ----------
  __syncthreads();
  __threadfence();
  if (tid == 0) *(volatile unsigned*)&g_arr1[c] = 1u;
  if (c == 0){
    if (tid < NB){ while (*(volatile unsigned*)&g_arr1[tid] < 1u) {} }
    __syncthreads();
    if (tid == 0){ __threadfence(); *(volatile unsigned*)&g_rel1 = 1u; }
  } else {
    if (tid == 0){ while (*(volatile unsigned*)&g_rel1 < 1u) {} __threadfence(); }
  }
  __syncthreads();

  // ---------- prologue GRU: cell(0) from x = emb[0], sign +1 ----------
  if (c < NGRU){
    if (tid < H) sx[tid] = __ldcg(&g_proc[tid]);
    __syncthreads();
    if (warp < HPC){
      int h = c*HPC + warp;
      if (h < H){
        const float4* wr = (const float4*)(fgmW + (size_t)h*H);
        const float4* xr = (const float4*)sx;
        float s = dot8(wr[lane], wr[lane+32], xr[lane], xr[lane+32]);
        #pragma unroll
        for (int o=16; o; o>>=1) s += __shfl_down_sync(0xffffffffu, s, o);
        if (lane == 0) sgbias[warp] = -(s + fgmb[h]);
      }
    }
    if (tid < HPC){
      int h = c*HPC + tid;
      sprocL[tid] = (h < H) ? sx[h] : 0.f;
    }
    __syncthreads();
    // L0 with x = emb row 0
    if (tid < H) sx[tid] = __ldg(&emb[tid]);
    __syncthreads();
    gru_dots(w0, sx, sgx, c);
    gru_act(sgx, sx, bih, bhh, g_xb, c);
    gru_barrier(c, tid, 1u);
    if (tid < H) sx[tid] = __ldcg(&g_xb[tid]);
    __syncthreads();
    gru_dots(w1, sx, sgx, c);
    gru_act(sgx, sx, bih + 3*H, bhh + 3*H, g_xc, c);
    gru_barrier(c, tid, 2u);
    if (tid < H) sx[tid] = __ldcg(&g_xc[tid]);
    __syncthreads();
    if (warp < HPC){
      int h = c*HPC + warp;
      float s = 0.f;
      if (h < H){
        const float4* wr = (const float4*)(wg + warp*H);
        const float4* xr = (const float4*)sx;
        s = dot8(wr[lane], wr[lane+32], xr[lane], xr[lane+32]);
      }
      #pragma unroll
      for (int o=16; o; o>>=1) s += __shfl_down_sync(0xffffffffu, s, o);
      if (lane == 0) sgx[warp] = s;
    }
    __syncthreads();
    if (tid < HPC){
      int h = c*HPC + tid;
      if (h < H){
        float gate = sigmoidf_(sgbias[tid] + sgx[tid]);
        g_cell[h] = gate*sprocL[tid] + (1.f-gate)*sx[h];
      }
    }
    // cell barrier epoch 1
    __syncthreads();
    if (tid == 0){ __threadfence(); *(volatile unsigned*)&g_arrC[c] = 1u; }
    if (c == 0){
      if (tid < NGRU){ while (*(volatile unsigned*)&g_arrC[tid] < 1u) {} }
      __syncthreads();
      if (tid == 0){ __threadfence(); *(volatile unsigned*)&g_relC = 1u; }
    }
    __syncthreads();
  }

  // ---------- main loop ----------
  for (int t = 0; t < T_STEPS; t++){
    // wait cell(t)
    if (tid == 0){
      while (*(volatile unsigned*)&g_relC < (unsigned)(t+1)) {}
      __threadfence();
    }
    __syncthreads();
    if (tid < H) scell[tid] = __ldcg(&g_cell[tid]);
    __syncthreads();

    // logits matvec: warp-per-row, 4 rows in flight
    {
      const float4* sc4 = (const float4*)scell;
      float4 c0 = sc4[lane], c1 = sc4[lane+32];
      for (int r = warp; r < myRows; r += NWARP*4){
        int r1 = r + NWARP, r2 = r + 2*NWARP, r3 = r + 3*NWARP;
        int q1 = min(r1, myRows-1), q2 = min(r2, myRows-1), q3 = min(r3, myRows-1);
        const float4* p0 = (const float4*)(fcW + (size_t)(base + r )*H);
        const float4* p1 = (const float4*)(fcW + (size_t)(base + q1)*H);
        const float4* p2 = (const float4*)(fcW + (size_t)(base + q2)*H);
        const float4* p3 = (const float4*)(fcW + (size_t)(base + q3)*H);
        float4 a0 = p0[lane], b0 = p0[lane+32];
        float4 a1 = p1[lane], b1 = p1[lane+32];
        float4 a2 = p2[lane], b2 = p2[lane+32];
        float4 a3 = p3[lane], b3 = p3[lane+32];
        float s0 = dot8(a0,b0,c0,c1);
        float s1 = dot8(a1,b1,c0,c1);
        float s2 = dot8(a2,b2,c0,c1);
        float s3 = dot8(a3,b3,c0,c1);
        #pragma unroll
        for (int o=16; o; o>>=1){
          s0 += __shfl_down_sync(0xffffffffu, s0, o);
          s1 += __shfl_down_sync(0xffffffffu, s1, o);
          s2 += __shfl_down_sync(0xffffffffu, s2, o);
          s3 += __shfl_down_sync(0xffffffffu, s3, o);
        }
        if (lane == 0){
          slogit[r] = s0 + sb[r];
          if (r1 < myRows) slogit[r1] = s1 + sb[r1];
          if (r2 < myRows) slogit[r2] = s2 + sb[r2];
          if (r3 < myRows) slogit[r3] = s3 + sb[r3];
        }
      }
    }
    __syncthreads();

    // block softmax stats
    {
      float v0 = (tid      < myRows) ? slogit[tid]      : -CUDART_INF_F;
      float v1 = (tid+TPB  < myRows) ? slogit[tid+TPB]  : -CUDART_INF_F;
      float m  = blockMaxB(fmaxf(v0, v1), swv);
      float z  = 0.f;
      if (tid     < myRows) z += expf(v0 - m);
      if (tid+TPB < myRows) z += expf(v1 - m);
      z = blockSumB(z, swv);
      if (tid == 0){ g_blkmax[c] = m; g_blksum[c] = z; }
    }
    // block top-10 (2-element sorted heads + tournament)
    {
      float h0v = -CUDART_INF_F, h1v = -CUDART_INF_F;
      int   h0i = 0x7FFFFFFF,    h1i = 0x7FFFFFFF;
      if (tid < myRows && s_hist[tid] != 0.f){ h0v = slogit[tid]; h0i = tid; }
      if (tid+TPB < myRows && s_hist[tid+TPB] != 0.f){
        float vv = slogit[tid+TPB]; int ii = tid+TPB;
        if (vv > h0v){ h1v = h0v; h1i = h0i; h0v = vv; h0i = ii; }
        else         { h1v = vv;  h1i = ii; }
      }
      for (int it = 0; it < KTOP; it++){
        float bv = h0v; int bi_ = h0i;
        bargmax(bv, bi_, swv, swi);
        if (tid == 0){
          bool ok = (bi_ != 0x7FFFFFFF);
          g_candv[c*KTOP + it] = bv;
          g_candi[c*KTOP + it] = ok ? (base + bi_) : 0x7FFFFFFF;
          g_candt[c*KTOP + it] = ok ? (int)s_int[bi_] : 0;
        }
        if (h0i == bi_){ h0v = h1v; h0i = h1i; h1v = -CUDART_INF_F; h1i = 0x7FFFFFFF; }
      }
    }
    __threadfence();
    if (tid == 0) *(volatile unsigned*)&g_arr1[c] = (unsigned)(t+2);

    // ===== SEL (CTA0 only) =====
    if (c == 0){
      if (tid < NB){ while (*(volatile unsigned*)&g_arr1[tid] < (unsigned)(t+2)) {} }
      __syncthreads();
      __threadfence();
      for (int i = tid; i < NCAND; i += TPB){
        scv[i] = __ldcg(&g_candv[i]);
        sci[i] = __ldcg(&g_candi[i]);
        sct[i] = (unsigned char)__ldcg(&g_candt[i]);
      }
      float bm = (tid < NB) ? __ldcg(&g_blkmax[tid]) : -CUDART_INF_F;
      float gmax = blockMaxB(bm, swv);
      float zz = (tid < NB) ? __ldcg(&g_blksum[tid]) * expf(bm - gmax) : 0.f;
      float Z = blockSumB(zz, swv);
      float pv = (tid < H) ? valW[tid] * scell[tid] : 0.f;
      pv = blockSumB(pv, swv);
      // tournament: 10 x flat argmax over 1480 in smem
      for (int it = 0; it < KTOP; it++){
        float v = -CUDART_INF_F; int ci = 0x7FFFFFFF; int pos = 0;
        for (int i = tid; i < NCAND; i += TPB){
          float vv = scv[i]; int ii = sci[i];
          if (vv > v || (vv == v && ii < ci)){ v = vv; ci = ii; pos = i; }
        }
        #pragma unroll
        for (int o=16; o; o>>=1){
          float ov = __shfl_down_sync(0xffffffffu, v, o);
          int   oi = __shfl_down_sync(0xffffffffu, ci, o);
          int   op = __shfl_down_sync(0xffffffffu, pos, o);
          if (ov > v || (ov == v && oi < ci)){ v = ov; ci = oi; pos = op; }
        }
        if (lane == 0){ swv[warp] = v; swi[warp] = ci; swp[warp] = pos; }
        __syncthreads();
        if (tid == 0){
          float bv = swv[0]; int bci = swi[0]; int bp = swp[0];
          #pragma unroll
          for (int w = 1; w < NWARP; w++){
            if (swv[w] > bv || (swv[w] == bv && swi[w] < bci)){
              bv = swv[w]; bci = swi[w]; bp = swp[w];
            }
          }
          s_topi[it] = bci;
          s_topt[it] = sct[bp];
          scv[bp] = -CUDART_INF_F;
        }
        __syncthreads();
      }
      if (tid == 0){
        int first = -1;
        #pragma unroll
        for (int r = 0; r < KTOP; r++)
          if (first < 0 && s_topt[r]) first = r;
        int hit = (first >= 0);
        int sel = hit ? s_topi[first] : s_topi[0];
        out[OUT_SEL + t] = (float)sel;
        out[OUT_HIT + t] = hit ? 1.f : 0.f;
        out[OUT_VAL + t] = pv + valb[0];
        g_gmaxS = gmax; g_invZS = 1.f/Z; g_selP = (sel<<1) | hit;
        __threadfence();
        *(volatile unsigned*)&g_selF = (unsigned)(t+1);
      }
      __syncthreads();
    }

    // ===== all CTAs: consume selection =====
    if (tid == 0){
      while (*(volatile unsigned*)&g_selF < (unsigned)(t+1)) {}
      __threadfence();
      int sp = __ldcg(&g_selP);
      s_sel = sp >> 1; s_hit = sp & 1; s_sign = (sp & 1) ? 1.f : -1.f;
      s_gm = __ldcg(&g_gmaxS); s_iz = __ldcg(&g_invZS);
      if ((sp & 1) && (sp>>1) >= base && (sp>>1) < base + myRows)
        s_hist[(sp>>1) - base] -= 1.f;
    }
    __syncthreads();
    // writeout probs(t) — overlaps GRU window
    {
      float gm = s_gm, iz = s_iz;
      for (int i = tid; i < myRows; i += TPB)
        __stcs(&out[(size_t)t*V + base + i], expf(slogit[i]-gm)*iz);
    }

    // ===== GRU -> cell(t+1) =====
    if (t < T_STEPS-1 && c < NGRU){
      if (tid < H) sx[tid] = s_sign * __ldg(&emb[(size_t)s_sel*H + tid]);
      __syncthreads();
      gru_dots(w0, sx, sgx, c);
      gru_act(sgx, sx, bih, bhh, g_xb, c);
      gru_barrier(c, tid, (unsigned)(2*t+3));
      if (tid < H) sx[tid] = __ldcg(&g_xb[tid]);
      __syncthreads();
      gru_dots(w1, sx, sgx, c);
      gru_act(sgx, sx, bih + 3*H, bhh + 3*H, g_xc, c);
      gru_barrier(c, tid, (unsigned)(2*t+4));
      if (tid < H) sx[tid] = __ldcg(&g_xc[tid]);
      __syncthreads();
      if (warp < HPC){
        int h = c*HPC + warp;
        float s = 0.f;
        if (h < H){
          const float4* wr = (const float4*)(wg + warp*H);
          const float4* xr = (const float4*)sx;
          s = dot8(wr[lane], wr[lane+32], xr[lane], xr[lane+32]);
        }
        #pragma unroll
        for (int o=16; o; o>>=1) s += __shfl_down_sync(0xffffffffu, s, o);
        if (lane == 0) sgx[warp] = s;
      }
      __syncthreads();
      if (tid < HPC){
        int h = c*HPC + tid;
        if (h < H){
          float gate = sigmoidf_(sgbias[tid] + sgx[tid]);
          g_cell[h] = gate*sprocL[tid] + (1.f-gate)*sx[h];
        }
      }
      __syncthreads();
      if (tid == 0){ __threadfence(); *(volatile unsigned*)&g_arrC[c] = (unsigned)(t+2); }
      if (c == 0){
        if (tid < NGRU){ while (*(volatile unsigned*)&g_arrC[tid] < (unsigned)(t+2)) {} }
        __syncthreads();
        if (tid == 0){ __threadfence(); *(volatile unsigned*)&g_relC = (unsigned)(t+2); }
      }
      __syncthreads();
    }
  }

  // ---------- epilogue: hist ----------
  for (int i = tid; i < myRows; i += TPB)
    __stcs(&out[OUT_HIST + base + i], s_hist[i]);
}

extern "C" void kernel_launch(void* const* d_in, const int* in_sizes, int n_in,
                              void* d_out, int out_size){
  (void)in_sizes; (void)n_in; (void)out_size;
  const float* interesting = (const float*)d_in[0];
  const float* masking     = (const float*)d_in[1];
  const float* mem         = (const float*)d_in[2];
  const float* emb         = (const float*)d_in[3];
  const float* Wih         = (const float*)d_in[4];
  /* d_in[5] = gru_Whh unused (hidden state always zero) */
  const float* bih         = (const float*)d_in[6];
  const float* bhh         = (const float*)d_in[7];
  const float* fcW         = (const float*)d_in[8];
  const float* fcb         = (const float*)d_in[9];
  const float* valW        = (const float*)d_in[10];
  const float* valb        = (const float*)d_in[11];
  const float* memW        = (const float*)d_in[12];
  const float* fgmW        = (const float*)d_in[13];
  const float* fgmb        = (const float*)d_in[14];
  const float* fgcW        = (const float*)d_in[15];
  float* out = (float*)d_out;

  k_reset<<<1, TPB>>>();
  k_persist<<<NB, TPB>>>(interesting, masking, mem, emb, Wih, bih, bhh,
                         fcW, fcb, valW, valb, memW, fgmW, fgmb, fgcW, out);
}

// round 7
// speedup vs baseline: 3.5290x; 1.0361x over previous
#include <cuda_runtime.h>
#include <math_constants.h>

#define V 100000
#define H 256
#define T_STEPS 64
#define NB 296                /* 2 CTAs per SM on 148 SMs */
#define TPB 512
#define NWARP 16
#define RPC 338               /* 296*338 = 100048 >= V */
#define KTOP 10
#define NCAND (NB*KTOP)       /* 2960 */
#define CPT 6                 /* ceil(NCAND/TPB) candidates per CTA0 thread */
#define HPC 3
#define NGRU 86

#define OUT_SEL   ((size_t)T_STEPS * V)
#define OUT_VAL   (OUT_SEL + T_STEPS)
#define OUT_HIT   (OUT_VAL + T_STEPS)
#define OUT_HIST  (OUT_HIT + T_STEPS)

// ---------------- device scratch ----------------
__device__ __align__(16) float g_cell[H];
__device__ __align__(16) float g_proc[H];
__device__ __align__(16) float g_xb[H];
__device__ __align__(16) float g_xc[H];
__device__ float g_blkmax[NB];
__device__ float g_blksum[NB];
__device__ float g_candv[NCAND];
__device__ int   g_candi[NCAND];
__device__ int   g_candt[NCAND];
__device__ float g_gmaxS, g_invZS;
__device__ int   g_selP;            // (sel<<1)|hit
__device__ unsigned g_arr1[NB];
__device__ unsigned g_rel1;
__device__ unsigned g_arrG[NGRU];
__device__ unsigned g_relG;
__device__ unsigned g_arrC[NGRU];
__device__ unsigned g_relC;
__device__ unsigned g_selF;

__device__ __forceinline__ float sigmoidf_(float x){ return 1.f/(1.f+expf(-x)); }
__device__ __forceinline__ float dot8(float4 a, float4 b, float4 x, float4 y){
  return a.x*x.x + a.y*x.y + a.z*x.z + a.w*x.w
       + b.x*y.x + b.y*y.y + b.z*y.z + b.w*y.w;
}

// ---------------- reset: absolute epochs each launch ----------------
__global__ __launch_bounds__(TPB) void k_reset(){
  int i = threadIdx.x;
  if (i < NB)   g_arr1[i] = 0u;
  if (i < NGRU){ g_arrG[i] = 0u; g_arrC[i] = 0u; }
  if (i == 0){ g_rel1 = 0u; g_relG = 0u; g_relC = 0u; g_selF = 0u; }
}

// block reductions (shfl two-level)
__device__ __forceinline__ float blockMaxB(float v, float* sw){
  int lane = threadIdx.x & 31, warp = threadIdx.x >> 5;
  #pragma unroll
  for (int o=16; o; o>>=1) v = fmaxf(v, __shfl_down_sync(0xffffffffu, v, o));
  if (lane == 0) sw[warp] = v;
  __syncthreads();
  if (warp == 0){
    float x = (lane < NWARP) ? sw[lane] : -CUDART_INF_F;
    #pragma unroll
    for (int o=8; o; o>>=1) x = fmaxf(x, __shfl_down_sync(0xffffffffu, x, o));
    if (lane == 0) sw[0] = x;
  }
  __syncthreads();
  float r = sw[0];
  __syncthreads();
  return r;
}
__device__ __forceinline__ float blockSumB(float v, float* sw){
  int lane = threadIdx.x & 31, warp = threadIdx.x >> 5;
  #pragma unroll
  for (int o=16; o; o>>=1) v += __shfl_down_sync(0xffffffffu, v, o);
  if (lane == 0) sw[warp] = v;
  __syncthreads();
  if (warp == 0){
    float x = (lane < NWARP) ? sw[lane] : 0.f;
    #pragma unroll
    for (int o=8; o; o>>=1) x += __shfl_down_sync(0xffffffffu, x, o);
    if (lane == 0) sw[0] = x;
  }
  __syncthreads();
  float r = sw[0];
  __syncthreads();
  return r;
}
__device__ __forceinline__ void bargmax(float &v, int &i, float* swv, int* swi){
  int lane = threadIdx.x & 31, warp = threadIdx.x >> 5;
  #pragma unroll
  for (int o=16; o; o>>=1){
    float ov = __shfl_down_sync(0xffffffffu, v, o);
    int   oi = __shfl_down_sync(0xffffffffu, i, o);
    if (ov > v || (ov == v && oi < i)){ v = ov; i = oi; }
  }
  if (lane == 0){ swv[warp] = v; swi[warp] = i; }
  __syncthreads();
  if (warp == 0){
    float x = (lane < NWARP) ? swv[lane] : -CUDART_INF_F;
    int  xi = (lane < NWARP) ? swi[lane] : 0x7FFFFFFF;
    #pragma unroll
    for (int o=8; o; o>>=1){
      float ov = __shfl_down_sync(0xffffffffu, x, o);
      int   oi = __shfl_down_sync(0xffffffffu, xi, o);
      if (ov > x || (ov == x && oi < xi)){ x = ov; xi = oi; }
    }
    if (lane == 0){ swv[0] = x; swi[0] = xi; }
  }
  __syncthreads();
  v = swv[0]; i = swi[0];
  __syncthreads();
}

// GRU sub-barrier among NGRU CTAs, absolute epoch e
__device__ __forceinline__ void gru_barrier(int c, int tid, unsigned e){
  __syncthreads();
  if (tid == 0){ __threadfence(); *(volatile unsigned*)&g_arrG[c] = e; }
  if (c == 0){
    if (tid < NGRU){ while (*(volatile unsigned*)&g_arrG[tid] < e) {} }
    __syncthreads();
    if (tid == 0){ __threadfence(); *(volatile unsigned*)&g_relG = e; }
  } else {
    if (tid == 0){ while (*(volatile unsigned*)&g_relG < e) {} __threadfence(); }
  }
  __syncthreads();
}

// 9 warps: dots for 3 h x 3 gates from smem weights against smem x
__device__ __forceinline__ void gru_dots(const float* Wsm, const float* sx, float* sgx, int c){
  int tid = threadIdx.x, lane = tid & 31, warp = tid >> 5;
  if (warp < 3*HPC){
    int a = warp / 3;
    int h = c*HPC + a;
    float s = 0.f;
    if (h < H){
      const float4* wr = (const float4*)(Wsm + warp*H);
      const float4* xr = (const float4*)sx;
      s = dot8(wr[lane], wr[lane+32], xr[lane], xr[lane+32]);
    }
    #pragma unroll
    for (int o=16; o; o>>=1) s += __shfl_down_sync(0xffffffffu, s, o);
    if (lane == 0) sgx[warp] = s;
  }
  __syncthreads();
}
__device__ __forceinline__ void gru_act(const float* sgx,
                                        const float* bi, const float* bh,
                                        float* xout_g, int c){
  int tid = threadIdx.x;
  if (tid < HPC){
    int h = c*HPC + tid;
    if (h < H){
      float r = sigmoidf_(sgx[tid*3+0] + bi[h]     + bh[h]);
      float z = sigmoidf_(sgx[tid*3+1] + bi[H+h]   + bh[H+h]);
      float n = tanhf   (sgx[tid*3+2] + bi[2*H+h] + r*bh[2*H+h]);
      xout_g[h] = (1.f - z) * n;
    }
  }
}

__global__ __launch_bounds__(TPB, 2)
void k_persist(const float* __restrict__ interesting, const float* __restrict__ masking,
               const float* __restrict__ mem, const float* __restrict__ emb,
               const float* __restrict__ Wih, const float* __restrict__ bih,
               const float* __restrict__ bhh, const float* __restrict__ fcW,
               const float* __restrict__ fcb, const float* __restrict__ valW,
               const float* __restrict__ valb, const float* __restrict__ memW,
               const float* __restrict__ fgmW, const float* __restrict__ fgmb,
               const float* __restrict__ fgcW, float* __restrict__ out){
  __shared__ __align__(16) float scell[H];
  __shared__ __align__(16) float sx[H];
  __shared__ float sb[RPC];
  __shared__ float slogit[RPC];
  __shared__ float s_hist[RPC];
  __shared__ unsigned char s_int[RPC];
  __shared__ __align__(16) float w0[3*HPC*H];
  __shared__ __align__(16) float w1[3*HPC*H];
  __shared__ __align__(16) float wg[HPC*H];
  __shared__ float swv[NWARP];
  __shared__ int   swi[NWARP];
  __shared__ int   swp[NWARP];
  __shared__ float sgx[3*HPC];
  __shared__ float sgbias[HPC];
  __shared__ float sprocL[HPC];
  __shared__ int   s_topi[KTOP];
  __shared__ unsigned char s_topt[KTOP];
  __shared__ int   s_win;
  __shared__ float s_gm, s_iz, s_sign;
  __shared__ int   s_sel;

  const int tid = threadIdx.x, lane = tid & 31, warp = tid >> 5;
  const int c = blockIdx.x;
  const int base = c * RPC;
  const int myRows = min(RPC, V - base);

  // ---------- prologue loads ----------
  for (int i = tid; i < myRows; i += TPB){
    sb[i] = fcb[base + i];
    s_hist[i] = masking[base + i];
    s_int[i] = (interesting[base + i] > 0.f) ? 1 : 0;
  }
  if (c < NGRU){
    for (int idx = tid; idx < 3*HPC*H; idx += TPB){
      int j = idx / H, col = idx % H;
      int a = j / 3, g = j % 3, h = c*HPC + a;
      float v0 = 0.f, v1 = 0.f;
      if (h < H){
        v0 = Wih[(size_t)(g*H + h)*H + col];
        v1 = Wih[(size_t)3*H*H + (size_t)(g*H + h)*H + col];
      }
      w0[idx] = v0; w1[idx] = v1;
    }
    for (int idx = tid; idx < HPC*H; idx += TPB){
      int a = idx / H, col = idx % H, h = c*HPC + a;
      wg[idx] = (h < H) ? fgcW[(size_t)h*H + col] : 0.f;
    }
  }
  // proc rows: CTA c handles row r=c (H=256 < NB=296 covers with c<H)
  for (int r = c; r < H; r += NB){
    const float4* m4 = (const float4*)mem;
    const float4* w4 = (const float4*)(memW + (size_t)r*V);
    float s = 0.f;
    for (int i = tid; i < V/4; i += TPB){
      float4 a = m4[i], b = __ldcs(&w4[i]);
      s += a.x*b.x + a.y*b.y + a.z*b.z + a.w*b.w;
    }
    s = blockSumB(s, swv);
    if (tid == 0) g_proc[r] = tanhf(s);
  }

  // ---------- full barrier (epoch 1) ----------
  __syncthreads();
  __threadfence();
  if (tid == 0) *(volatile unsigned*)&g_arr1[c] = 1u;
  if (c == 0){
    if (tid < NB){ while (*(volatile unsigned*)&g_arr1[tid] < 1u) {} }
    __syncthreads();
    if (tid == 0){ __threadfence(); *(volatile unsigned*)&g_rel1 = 1u; }
  } else {
    if (tid == 0){ while (*(volatile unsigned*)&g_rel1 < 1u) {} __threadfence(); }
  }
  __syncthreads();

  // ---------- prologue GRU: cell(0) from x = emb[0] ----------
  if (c < NGRU){
    if (tid < H) sx[tid] = __ldcg(&g_proc[tid]);
    __syncthreads();
    if (warp < HPC){
      int h = c*HPC + warp;
      if (h < H){
        const float4* wr = (const float4*)(fgmW + (size_t)h*H);
        const float4* xr = (const float4*)sx;
        float s = dot8(wr[lane], wr[lane+32], xr[lane], xr[lane+32]);
        #pragma unroll
        for (int o=16; o; o>>=1) s += __shfl_down_sync(0xffffffffu, s, o);
        if (lane == 0) sgbias[warp] = -(s + fgmb[h]);
      }
    }
    if (tid < HPC){
      int h = c*HPC + tid;
      sprocL[tid] = (h < H) ? sx[h] : 0.f;
    }
    __syncthreads();
    if (tid < H) sx[tid] = __ldg(&emb[tid]);
    __syncthreads();
    gru_dots(w0, sx, sgx, c);
    gru_act(sgx, bih, bhh, g_xb, c);
    gru_barrier(c, tid, 1u);
    if (tid < H) sx[tid] = __ldcg(&g_xb[tid]);
    __syncthreads();
    gru_dots(w1, sx, sgx, c);
    gru_act(sgx, bih + 3*H, bhh + 3*H, g_xc, c);
    gru_barrier(c, tid, 2u);
    if (tid < H) sx[tid] = __ldcg(&g_xc[tid]);
    __syncthreads();
    if (warp < HPC){
      int h = c*HPC + warp;
      float s = 0.f;
      if (h < H){
        const float4* wr = (const float4*)(wg + warp*H);
        const float4* xr = (const float4*)sx;
        s = dot8(wr[lane], wr[lane+32], xr[lane], xr[lane+32]);
      }
      #pragma unroll
      for (int o=16; o; o>>=1) s += __shfl_down_sync(0xffffffffu, s, o);
      if (lane == 0) sgx[warp] = s;
    }
    __syncthreads();
    if (tid < HPC){
      int h = c*HPC + tid;
      if (h < H){
        float gate = sigmoidf_(sgbias[tid] + sgx[tid]);
        g_cell[h] = gate*sprocL[tid] + (1.f-gate)*sx[h];
      }
    }
    __syncthreads();
    if (tid == 0){ __threadfence(); *(volatile unsigned*)&g_arrC[c] = 1u; }
    if (c == 0){
      if (tid < NGRU){ while (*(volatile unsigned*)&g_arrC[tid] < 1u) {} }
      __syncthreads();
      if (tid == 0){ __threadfence(); *(volatile unsigned*)&g_relC = 1u; }
    }
    __syncthreads();
  }

  // ---------- main loop ----------
  for (int t = 0; t < T_STEPS; t++){
    // wait cell(t)
    if (tid == 0){
      while (*(volatile unsigned*)&g_relC < (unsigned)(t+1)) {}
      __threadfence();
    }
    __syncthreads();
    if (tid < H) scell[tid] = __ldcg(&g_cell[tid]);
    __syncthreads();

    // logits matvec: warp-per-row, 4 rows in flight; 2 CTAs/SM -> 32 warps/SM MLP
    {
      const float4* sc4 = (const float4*)scell;
      float4 c0 = sc4[lane], c1 = sc4[lane+32];
      for (int r = warp; r < myRows; r += NWARP*4){
        int r1 = r + NWARP, r2 = r + 2*NWARP, r3 = r + 3*NWARP;
        int q1 = min(r1, myRows-1), q2 = min(r2, myRows-1), q3 = min(r3, myRows-1);
        const float4* p0 = (const float4*)(fcW + (size_t)(base + r )*H);
        const float4* p1 = (const float4*)(fcW + (size_t)(base + q1)*H);
        const float4* p2 = (const float4*)(fcW + (size_t)(base + q2)*H);
        const float4* p3 = (const float4*)(fcW + (size_t)(base + q3)*H);
        float4 a0 = p0[lane], b0 = p0[lane+32];
        float4 a1 = p1[lane], b1 = p1[lane+32];
        float4 a2 = p2[lane], b2 = p2[lane+32];
        float4 a3 = p3[lane], b3 = p3[lane+32];
        float s0 = dot8(a0,b0,c0,c1);
        float s1 = dot8(a1,b1,c0,c1);
        float s2 = dot8(a2,b2,c0,c1);
        float s3 = dot8(a3,b3,c0,c1);
        #pragma unroll
        for (int o=16; o; o>>=1){
          s0 += __shfl_down_sync(0xffffffffu, s0, o);
          s1 += __shfl_down_sync(0xffffffffu, s1, o);
          s2 += __shfl_down_sync(0xffffffffu, s2, o);
          s3 += __shfl_down_sync(0xffffffffu, s3, o);
        }
        if (lane == 0){
          slogit[r] = s0 + sb[r];
          if (r1 < myRows) slogit[r1] = s1 + sb[r1];
          if (r2 < myRows) slogit[r2] = s2 + sb[r2];
          if (r3 < myRows) slogit[r3] = s3 + sb[r3];
        }
      }
    }
    __syncthreads();

    // block softmax stats (<=1 row per thread)
    {
      float v0 = (tid < myRows) ? slogit[tid] : -CUDART_INF_F;
      float m  = blockMaxB(v0, swv);
      float z  = (tid < myRows) ? expf(v0 - m) : 0.f;
      z = blockSumB(z, swv);
      if (tid == 0){ g_blkmax[c] = m; g_blksum[c] = z; }
    }
    // block top-10 (one candidate per thread)
    {
      float hv = -CUDART_INF_F; int hi = 0x7FFFFFFF;
      if (tid < myRows && s_hist[tid] != 0.f){ hv = slogit[tid]; hi = tid; }
      for (int it = 0; it < KTOP; it++){
        float bv = hv; int bi_ = hi;
        bargmax(bv, bi_, swv, swi);
        if (tid == 0){
          bool ok = (bi_ != 0x7FFFFFFF);
          g_candv[c*KTOP + it] = bv;
          g_candi[c*KTOP + it] = ok ? (base + bi_) : 0x7FFFFFFF;
          g_candt[c*KTOP + it] = ok ? (int)s_int[bi_] : 0;
        }
        if (hi == bi_) hv = -CUDART_INF_F;
      }
    }
    __threadfence();
    if (tid == 0) *(volatile unsigned*)&g_arr1[c] = (unsigned)(t+2);

    // ===== SEL (CTA0 only) =====
    if (c == 0){
      if (tid < NB){ while (*(volatile unsigned*)&g_arr1[tid] < (unsigned)(t+2)) {} }
      __syncthreads();
      __threadfence();
      // per-thread candidate cache in registers
      float lv[CPT]; int lii[CPT];
      #pragma unroll
      for (int k = 0; k < CPT; k++){
        int i = tid + k*TPB;
        if (i < NCAND){ lv[k] = __ldcg(&g_candv[i]); lii[k] = __ldcg(&g_candi[i]); }
        else { lv[k] = -CUDART_INF_F; lii[k] = 0x7FFFFFFF; }
      }
      float bm = (tid < NB) ? __ldcg(&g_blkmax[tid]) : -CUDART_INF_F;
      float gmax = blockMaxB(bm, swv);
      float zz = (tid < NB) ? __ldcg(&g_blksum[tid]) * expf(bm - gmax) : 0.f;
      float Z = blockSumB(zz, swv);
      float pv = (tid < H) ? valW[tid] * scell[tid] : 0.f;
      pv = blockSumB(pv, swv);
      // 10 tournament rounds entirely from registers
      for (int it = 0; it < KTOP; it++){
        float v = -CUDART_INF_F; int ci = 0x7FFFFFFF; int slot = 0;
        #pragma unroll
        for (int k = 0; k < CPT; k++){
          if (lv[k] > v || (lv[k] == v && lii[k] < ci)){ v = lv[k]; ci = lii[k]; slot = k; }
        }
        int pack = (tid << 3) | slot;
        #pragma unroll
        for (int o=16; o; o>>=1){
          float ov = __shfl_down_sync(0xffffffffu, v, o);
          int   oi = __shfl_down_sync(0xffffffffu, ci, o);
          int   op = __shfl_down_sync(0xffffffffu, pack, o);
          if (ov > v || (ov == v && oi < ci)){ v = ov; ci = oi; pack = op; }
        }
        if (lane == 0){ swv[warp] = v; swi[warp] = ci; swp[warp] = pack; }
        __syncthreads();
        if (tid == 0){
          float bv = swv[0]; int bci = swi[0]; int bp = swp[0];
          #pragma unroll
          for (int w = 1; w < NWARP; w++){
            if (swv[w] > bv || (swv[w] == bv && swi[w] < bci)){
              bv = swv[w]; bci = swi[w]; bp = swp[w];
            }
          }
          s_topi[it] = bci;
          int pos = (bp >> 3) + (bp & 7) * TPB;
          s_topt[it] = (unsigned char)__ldcg(&g_candt[pos]);
          s_win = bp;
        }
        __syncthreads();
        if (tid == (s_win >> 3)) lv[s_win & 7] = -CUDART_INF_F;
      }
      if (tid == 0){
        int first = -1;
        #pragma unroll
        for (int r = 0; r < KTOP; r++)
          if (first < 0 && s_topt[r]) first = r;
        int hit = (first >= 0);
        int sel = hit ? s_topi[first] : s_topi[0];
        out[OUT_SEL + t] = (float)sel;
        out[OUT_HIT + t] = hit ? 1.f : 0.f;
        out[OUT_VAL + t] = pv + valb[0];
        g_gmaxS = gmax; g_invZS = 1.f/Z; g_selP = (sel<<1) | hit;
        __threadfence();
        *(volatile unsigned*)&g_selF = (unsigned)(t+1);
      }
      __syncthreads();
    }

    // ===== all CTAs: consume selection =====
    if (tid == 0){
      while (*(volatile unsigned*)&g_selF < (unsigned)(t+1)) {}
      __threadfence();
      int sp = __ldcg(&g_selP);
      s_sel = sp >> 1; s_sign = (sp & 1) ? 1.f : -1.f;
      s_gm = __ldcg(&g_gmaxS); s_iz = __ldcg(&g_invZS);
      if ((sp & 1) && (sp>>1) >= base && (sp>>1) < base + myRows)
        s_hist[(sp>>1) - base] -= 1.f;
    }
    __syncthreads();
    // writeout probs(t) — overlaps GRU window
    {
      float gm = s_gm, iz = s_iz;
      for (int i = tid; i < myRows; i += TPB)
        __stcs(&out[(size_t)t*V + base + i], expf(slogit[i]-gm)*iz);
    }

    // ===== GRU -> cell(t+1) =====
    if (t < T_STEPS-1 && c < NGRU){
      if (tid < H) sx[tid] = s_sign * __ldg(&emb[(size_t)s_sel*H + tid]);
      __syncthreads();
      gru_dots(w0, sx, sgx, c);
      gru_act(sgx, bih, bhh, g_xb, c);
      gru_barrier(c, tid, (unsigned)(2*t+3));
      if (tid < H) sx[tid] = __ldcg(&g_xb[tid]);
      __syncthreads();
      gru_dots(w1, sx, sgx, c);
      gru_act(sgx, bih + 3*H, bhh + 3*H, g_xc, c);
      gru_barrier(c, tid, (unsigned)(2*t+4));
      if (tid < H) sx[tid] = __ldcg(&g_xc[tid]);
      __syncthreads();
      if (warp < HPC){
        int h = c*HPC + warp;
        float s = 0.f;
        if (h < H){
          const float4* wr = (const float4*)(wg + warp*H);
          const float4* xr = (const float4*)sx;
          s = dot8(wr[lane], wr[lane+32], xr[lane], xr[lane+32]);
        }
        #pragma unroll
        for (int o=16; o; o>>=1) s += __shfl_down_sync(0xffffffffu, s, o);
        if (lane == 0) sgx[warp] = s;
      }
      __syncthreads();
      if (tid < HPC){
        int h = c*HPC + tid;
        if (h < H){
          float gate = sigmoidf_(sgbias[tid] + sgx[tid]);
          g_cell[h] = gate*sprocL[tid] + (1.f-gate)*sx[h];
        }
      }
      __syncthreads();
      if (tid == 0){ __threadfence(); *(volatile unsigned*)&g_arrC[c] = (unsigned)(t+2); }
      if (c == 0){
        if (tid < NGRU){ while (*(volatile unsigned*)&g_arrC[tid] < (unsigned)(t+2)) {} }
        __syncthreads();
        if (tid == 0){ __threadfence(); *(volatile unsigned*)&g_relC = (unsigned)(t+2); }
      }
      __syncthreads();
    }
  }

  // ---------- epilogue: hist ----------
  for (int i = tid; i < myRows; i += TPB)
    __stcs(&out[OUT_HIST + base + i], s_hist[i]);
}

extern "C" void kernel_launch(void* const* d_in, const int* in_sizes, int n_in,
                              void* d_out, int out_size){
  (void)in_sizes; (void)n_in; (void)out_size;
  const float* interesting = (const float*)d_in[0];
  const float* masking     = (const float*)d_in[1];
  const float* mem         = (const float*)d_in[2];
  const float* emb         = (const float*)d_in[3];
  const float* Wih         = (const float*)d_in[4];
  /* d_in[5] = gru_Whh unused (hidden state always zero) */
  const float* bih         = (const float*)d_in[6];
  const float* bhh         = (const float*)d_in[7];
  const float* fcW         = (const float*)d_in[8];
  const float* fcb         = (const float*)d_in[9];
  const float* valW        = (const float*)d_in[10];
  const float* valb        = (const float*)d_in[11];
  const float* memW        = (const float*)d_in[12];
  const float* fgmW        = (const float*)d_in[13];
  const float* fgmb        = (const float*)d_in[14];
  const float* fgcW        = (const float*)d_in[15];
  float* out = (float*)d_out;

  k_reset<<<1, TPB>>>();
  k_persist<<<NB, TPB>>>(interesting, masking, mem, emb, Wih, bih, bhh,
                         fcW, fcb, valW, valb, memW, fgmW, fgmb, fgcW, out);
}